// round 2
// baseline (speedup 1.0000x reference)
#include <cuda_runtime.h>
#include <cuda_bf16.h>
#include <math.h>

// ---------------- problem constants ----------------
#define BB   16
#define TT   512
#define SS   512
#define DDIM 512
#define HH   8
#define DHH  64
#define FFF  2048
#define NLAYERS 6
#define MROWS (BB*TT)   // 8192 rows everywhere (T == S)

// ---------------- scratch (device globals; no allocs allowed) ----------------
__device__ __align__(256) float g_mem[BB*SS*DDIM];
__device__ __align__(256) float g_t  [MROWS*DDIM];
__device__ __align__(256) float g_x  [MROWS*DDIM];
__device__ __align__(256) float g_q  [MROWS*DDIM];
__device__ __align__(256) float g_k  [MROWS*DDIM];
__device__ __align__(256) float g_v  [MROWS*DDIM];
__device__ __align__(256) float g_ao [MROWS*DDIM];
__device__ __align__(256) float g_ff [MROWS*FFF];

// ---------------- GEMM: C[M,N] = act(A[M,K] @ W[K,N] + bias (+ res)) ---------
// 128x128 block tile, 16 k-slice, 8x8 register tile per thread, 256 threads.
// M, N multiples of 128; K multiple of 16 (true for all calls here).
// act: 0 = none, 1 = leaky_relu(0.01), 2 = 2*leaky_relu(0.01)
__global__ __launch_bounds__(256, 2)
void gemm_kernel(const float* __restrict__ A, const float* __restrict__ W,
                 const float* __restrict__ bias, const float* __restrict__ res,
                 float* __restrict__ C, int K, int N, int act)
{
    __shared__ float As[16][129];   // [k][m], padded
    __shared__ float Bs[16][128];   // [k][n]

    const int tid = threadIdx.x;
    const int tx  = tid & 15;       // n-sub
    const int ty  = tid >> 4;       // m-sub
    const int m0  = blockIdx.y * 128;
    const int n0  = blockIdx.x * 128;

    const float* Ab = A + (size_t)m0 * K;
    const float* Wb = W + n0;

    float acc[8][8];
#pragma unroll
    for (int i = 0; i < 8; i++)
#pragma unroll
        for (int j = 0; j < 8; j++) acc[i][j] = 0.f;

    for (int kt = 0; kt < K; kt += 16) {
        // load A tile 128x16 (512 float4)
#pragma unroll
        for (int w = 0; w < 2; w++) {
            int i4 = tid + w * 256;
            int mm = i4 >> 2;
            int kc = (i4 & 3) << 2;
            float4 a4 = *(const float4*)(Ab + (size_t)mm * K + kt + kc);
            As[kc + 0][mm] = a4.x;
            As[kc + 1][mm] = a4.y;
            As[kc + 2][mm] = a4.z;
            As[kc + 3][mm] = a4.w;
        }
        // load W tile 16x128 (512 float4)
#pragma unroll
        for (int w = 0; w < 2; w++) {
            int i4 = tid + w * 256;
            int kk = i4 >> 5;
            int nn = (i4 & 31) << 2;
            *(float4*)(&Bs[kk][nn]) = *(const float4*)(Wb + (size_t)(kt + kk) * N + nn);
        }
        __syncthreads();

#pragma unroll
        for (int kk = 0; kk < 16; kk++) {
            float a[8];
#pragma unroll
            for (int i = 0; i < 8; i++) a[i] = As[kk][ty * 8 + i];
            float4 b0 = *(const float4*)(&Bs[kk][tx * 8]);
            float4 b1 = *(const float4*)(&Bs[kk][tx * 8 + 4]);
            float b[8] = {b0.x, b0.y, b0.z, b0.w, b1.x, b1.y, b1.z, b1.w};
#pragma unroll
            for (int i = 0; i < 8; i++)
#pragma unroll
                for (int j = 0; j < 8; j++)
                    acc[i][j] = fmaf(a[i], b[j], acc[i][j]);
        }
        __syncthreads();
    }

    // epilogue
    const int cn = n0 + tx * 8;
    float4 bi0 = *(const float4*)(bias + cn);
    float4 bi1 = *(const float4*)(bias + cn + 4);
    float bb[8] = {bi0.x, bi0.y, bi0.z, bi0.w, bi1.x, bi1.y, bi1.z, bi1.w};

#pragma unroll
    for (int i = 0; i < 8; i++) {
        int m = m0 + ty * 8 + i;
        float v[8];
#pragma unroll
        for (int j = 0; j < 8; j++) v[j] = acc[i][j] + bb[j];
        if (res) {
            float4 r0 = *(const float4*)(res + (size_t)m * N + cn);
            float4 r1 = *(const float4*)(res + (size_t)m * N + cn + 4);
            v[0] += r0.x; v[1] += r0.y; v[2] += r0.z; v[3] += r0.w;
            v[4] += r1.x; v[5] += r1.y; v[6] += r1.z; v[7] += r1.w;
        }
        if (act == 1) {
#pragma unroll
            for (int j = 0; j < 8; j++) v[j] = v[j] > 0.f ? v[j] : 0.01f * v[j];
        } else if (act == 2) {
#pragma unroll
            for (int j = 0; j < 8; j++) {
                float lr = v[j] > 0.f ? v[j] : 0.01f * v[j];
                v[j] = lr + lr;
            }
        }
        float4 o0 = make_float4(v[0], v[1], v[2], v[3]);
        float4 o1 = make_float4(v[4], v[5], v[6], v[7]);
        *(float4*)(C + (size_t)m * N + cn)     = o0;
        *(float4*)(C + (size_t)m * N + cn + 4) = o1;
    }
}

// ---------------- LayerNorm over last dim (512) ----------------
__global__ void ln_kernel(const float* __restrict__ X, const float* __restrict__ w,
                          const float* __restrict__ b, float* __restrict__ Y)
{
    const int row = blockIdx.x;
    const int tid = threadIdx.x;  // 128 threads, 4 elements each
    float4 v = ((const float4*)(X + (size_t)row * 512))[tid];
    float s  = v.x + v.y + v.z + v.w;
    float ss = v.x * v.x + v.y * v.y + v.z * v.z + v.w * v.w;
#pragma unroll
    for (int o = 16; o > 0; o >>= 1) {
        s  += __shfl_xor_sync(0xffffffffu, s,  o);
        ss += __shfl_xor_sync(0xffffffffu, ss, o);
    }
    __shared__ float rs[4], rss[4];
    int wid = tid >> 5, lane = tid & 31;
    if (lane == 0) { rs[wid] = s; rss[wid] = ss; }
    __syncthreads();
    s  = rs[0] + rs[1] + rs[2] + rs[3];
    ss = rss[0] + rss[1] + rss[2] + rss[3];
    float mean = s * (1.f / 512.f);
    float var  = ss * (1.f / 512.f) - mean * mean;
    float inv  = rsqrtf(var + 1e-5f);
    float4 wv = ((const float4*)w)[tid];
    float4 bv = ((const float4*)b)[tid];
    float4 y;
    y.x = (v.x - mean) * inv * wv.x + bv.x;
    y.y = (v.y - mean) * inv * wv.y + bv.y;
    y.z = (v.z - mean) * inv * wv.z + bv.z;
    y.w = (v.w - mean) * inv * wv.w + bv.w;
    ((float4*)(Y + (size_t)row * 512))[tid] = y;
}

// ---------------- fused attention ----------------
// Layout: Q/K/V/O all [B*H][512][64] contiguous (== flat [B*L, D] GEMM output,
// because the reference reshape is a pure reinterpretation).
// Block = (qtile of 64 queries) x (one bh). 256 threads: thread (r, seg) owns
// query row r (0..63) and 16-wide slice seg (0..3) of keys/dh.
// Online softmax with score scale 1/32 and mask value -1e9 (matches reference).
#define ALD 68
#define ATTN_SMEM (4 * 64 * ALD * 4)

__global__ __launch_bounds__(256)
void attn_kernel(const float* __restrict__ Q, const float* __restrict__ K,
                 const float* __restrict__ V, float* __restrict__ O, int causal)
{
    extern __shared__ float sm[];
    float* Qs = sm;
    float* Ks = sm + 64 * ALD;
    float* Vs = sm + 2 * 64 * ALD;
    float* Ps = sm + 3 * 64 * ALD;

    const int qt  = blockIdx.x;   // 0..7
    const int bh  = blockIdx.y;   // 0..127
    const int tid = threadIdx.x;

    const float* Qb = Q + (size_t)bh * 512 * 64 + (size_t)qt * 64 * 64;
    const float* Kb = K + (size_t)bh * 512 * 64;
    const float* Vb = V + (size_t)bh * 512 * 64;
    float*       Ob = O + (size_t)bh * 512 * 64 + (size_t)qt * 64 * 64;

    // load Q tile (64x64)
#pragma unroll
    for (int w = 0; w < 4; w++) {
        int i4 = tid + w * 256;
        int rr = i4 >> 4;
        int c  = (i4 & 15) << 2;
        *(float4*)(Qs + rr * ALD + c) = *(const float4*)(Qb + rr * 64 + c);
    }

    const int r   = tid >> 2;  // 0..63
    const int seg = tid & 3;   // 0..3
    float m = -INFINITY, lsum = 0.f;
    float acc[16];
#pragma unroll
    for (int i = 0; i < 16; i++) acc[i] = 0.f;

    const int ktmax = causal ? qt : 7;
    for (int kt = 0; kt <= ktmax; kt++) {
        __syncthreads();  // protect K/V/P reuse from previous iteration
#pragma unroll
        for (int w = 0; w < 4; w++) {
            int i4 = tid + w * 256;
            int rr = i4 >> 4;
            int c  = (i4 & 15) << 2;
            *(float4*)(Ks + rr * ALD + c) = *(const float4*)(Kb + (kt * 64 + rr) * 64 + c);
            *(float4*)(Vs + rr * ALD + c) = *(const float4*)(Vb + (kt * 64 + rr) * 64 + c);
        }
        __syncthreads();

        // scores for keys j = seg*16 + kk
        float s[16];
#pragma unroll
        for (int i = 0; i < 16; i++) s[i] = 0.f;
#pragma unroll
        for (int c4 = 0; c4 < 16; c4++) {
            float4 q4 = *(const float4*)(Qs + r * ALD + c4 * 4);
#pragma unroll
            for (int kk = 0; kk < 16; kk++) {
                float4 k4 = *(const float4*)(Ks + (seg * 16 + kk) * ALD + c4 * 4);
                s[kk] = fmaf(q4.x, k4.x, s[kk]);
                s[kk] = fmaf(q4.y, k4.y, s[kk]);
                s[kk] = fmaf(q4.z, k4.z, s[kk]);
                s[kk] = fmaf(q4.w, k4.w, s[kk]);
            }
        }

        float mt = -INFINITY;
#pragma unroll
        for (int kk = 0; kk < 16; kk++) {
            float sv = s[kk] * 0.03125f;   // / (DH/2) == /32
            if (causal && kt == qt && (seg * 16 + kk) > r) sv = -1e9f;
            s[kk] = sv;
            mt = fmaxf(mt, sv);
        }
        mt = fmaxf(mt, __shfl_xor_sync(0xffffffffu, mt, 1));
        mt = fmaxf(mt, __shfl_xor_sync(0xffffffffu, mt, 2));
        float mnew = fmaxf(m, mt);
        float f = (m == -INFINITY) ? 0.f : __expf(m - mnew);
        lsum *= f;
#pragma unroll
        for (int i = 0; i < 16; i++) acc[i] *= f;

        float ps = 0.f;
#pragma unroll
        for (int kk = 0; kk < 16; kk++) {
            float p = __expf(s[kk] - mnew);
            ps += p;
            Ps[r * ALD + seg * 16 + kk] = p;
        }
        lsum += ps;
        m = mnew;
        __syncthreads();

        // acc[i] (dh = seg*16+i) += sum_j P[r][j] * V[j][dh]
#pragma unroll 8
        for (int j = 0; j < 64; j++) {
            float pj = Ps[r * ALD + j];
            const float* vrow = Vs + j * ALD + seg * 16;
            float4 v0 = *(const float4*)(vrow);
            float4 v1 = *(const float4*)(vrow + 4);
            float4 v2 = *(const float4*)(vrow + 8);
            float4 v3 = *(const float4*)(vrow + 12);
            acc[0]  = fmaf(pj, v0.x, acc[0]);  acc[1]  = fmaf(pj, v0.y, acc[1]);
            acc[2]  = fmaf(pj, v0.z, acc[2]);  acc[3]  = fmaf(pj, v0.w, acc[3]);
            acc[4]  = fmaf(pj, v1.x, acc[4]);  acc[5]  = fmaf(pj, v1.y, acc[5]);
            acc[6]  = fmaf(pj, v1.z, acc[6]);  acc[7]  = fmaf(pj, v1.w, acc[7]);
            acc[8]  = fmaf(pj, v2.x, acc[8]);  acc[9]  = fmaf(pj, v2.y, acc[9]);
            acc[10] = fmaf(pj, v2.z, acc[10]); acc[11] = fmaf(pj, v2.w, acc[11]);
            acc[12] = fmaf(pj, v3.x, acc[12]); acc[13] = fmaf(pj, v3.y, acc[13]);
            acc[14] = fmaf(pj, v3.z, acc[14]); acc[15] = fmaf(pj, v3.w, acc[15]);
        }
    }

    lsum += __shfl_xor_sync(0xffffffffu, lsum, 1);
    lsum += __shfl_xor_sync(0xffffffffu, lsum, 2);
    float inv = 1.f / lsum;
    float* orow = Ob + r * 64 + seg * 16;
#pragma unroll
    for (int u = 0; u < 4; u++) {
        float4 o = make_float4(acc[u * 4 + 0] * inv, acc[u * 4 + 1] * inv,
                               acc[u * 4 + 2] * inv, acc[u * 4 + 3] * inv);
        *(float4*)(orow + u * 4) = o;
    }
}

// ---------------- orchestration ----------------
extern "C" void kernel_launch(void* const* d_in, const int* in_sizes, int n_in,
                              void* d_out, int out_size)
{
    const float* memory   = (const float*)d_in[0];
    const float* target   = (const float*)d_in[1];
    // d_in[2] = mask (int32) — causal, hard-coded in attn_kernel
    const float* expand_w = (const float*)d_in[3];
    const float* expand_b = (const float*)d_in[4];
    const float* ln_w     = (const float*)d_in[5];
    const float* ln_b     = (const float*)d_in[6];
    const float* attn_w   = (const float*)d_in[7];
    const float* attn_b   = (const float*)d_in[8];
    const float* ff_w1    = (const float*)d_in[9];
    const float* ff_b1    = (const float*)d_in[10];
    const float* ff_w2    = (const float*)d_in[11];
    const float* ff_b2    = (const float*)d_in[12];
    float* out = (float*)d_out;

    float *mem, *t, *x, *q, *k, *v, *ao, *ff;
    cudaGetSymbolAddress((void**)&mem, g_mem);
    cudaGetSymbolAddress((void**)&t,   g_t);
    cudaGetSymbolAddress((void**)&x,   g_x);
    cudaGetSymbolAddress((void**)&q,   g_q);
    cudaGetSymbolAddress((void**)&k,   g_k);
    cudaGetSymbolAddress((void**)&v,   g_v);
    cudaGetSymbolAddress((void**)&ao,  g_ao);
    cudaGetSymbolAddress((void**)&ff,  g_ff);

    cudaFuncSetAttribute(attn_kernel, cudaFuncAttributeMaxDynamicSharedMemorySize, ATTN_SMEM);

    const dim3 g512(512 / 128, MROWS / 128);    // (4, 64)
    const dim3 g2048(2048 / 128, MROWS / 128);  // (16, 64)
    const dim3 gattn(8, BB * HH);               // (qtiles, B*H)

    // memory expansion: mem = lrelu(memory @ expand_w + expand_b)
    gemm_kernel<<<g512, 256>>>(memory, expand_w, expand_b, nullptr, mem, 128, 512, 1);

    const float* tin = target;
    for (int l = 0; l < NLAYERS; l++) {
        const float* aw = attn_w + (size_t)l * 2 * 4 * DDIM * DDIM;
        const float* ab = attn_b + (size_t)l * 2 * 4 * DDIM;
        const float* lw = ln_w + (size_t)l * 3 * DDIM;
        const float* lb = ln_b + (size_t)l * 3 * DDIM;

        // --- self attention (causal) ---
        ln_kernel<<<MROWS, 128>>>(tin, lw, lb, x);
        gemm_kernel<<<g512, 256>>>(x, aw + 0 * DDIM * DDIM, ab + 0 * DDIM, nullptr, q, 512, 512, 0);
        gemm_kernel<<<g512, 256>>>(x, aw + 1 * DDIM * DDIM, ab + 1 * DDIM, nullptr, k, 512, 512, 0);
        gemm_kernel<<<g512, 256>>>(x, aw + 2 * DDIM * DDIM, ab + 2 * DDIM, nullptr, v, 512, 512, 0);
        attn_kernel<<<gattn, 256, ATTN_SMEM>>>(q, k, v, ao, 1);
        gemm_kernel<<<g512, 256>>>(ao, aw + 3 * DDIM * DDIM, ab + 3 * DDIM, x, t, 512, 512, 0);

        // --- cross attention (no mask) ---
        const float* aw2 = aw + 4 * DDIM * DDIM;
        const float* ab2 = ab + 4 * DDIM;
        ln_kernel<<<MROWS, 128>>>(t, lw + DDIM, lb + DDIM, x);
        gemm_kernel<<<g512, 256>>>(x,   aw2 + 0 * DDIM * DDIM, ab2 + 0 * DDIM, nullptr, q, 512, 512, 0);
        gemm_kernel<<<g512, 256>>>(mem, aw2 + 1 * DDIM * DDIM, ab2 + 1 * DDIM, nullptr, k, 512, 512, 0);
        gemm_kernel<<<g512, 256>>>(mem, aw2 + 2 * DDIM * DDIM, ab2 + 2 * DDIM, nullptr, v, 512, 512, 0);
        attn_kernel<<<gattn, 256, ATTN_SMEM>>>(q, k, v, ao, 0);
        gemm_kernel<<<g512, 256>>>(ao, aw2 + 3 * DDIM * DDIM, ab2 + 3 * DDIM, x, t, 512, 512, 0);

        // --- feed-forward: t = 2*lrelu(lrelu(x@w1+b1)@w2+b2) (no residual) ---
        ln_kernel<<<MROWS, 128>>>(t, lw + 2 * DDIM, lb + 2 * DDIM, x);
        gemm_kernel<<<g2048, 256>>>(x, ff_w1 + (size_t)l * DDIM * FFF, ff_b1 + (size_t)l * FFF,
                                    nullptr, ff, 512, 2048, 1);
        float* dst = (l == NLAYERS - 1) ? out : t;
        gemm_kernel<<<g512, 256>>>(ff, ff_w2 + (size_t)l * FFF * DDIM, ff_b2 + (size_t)l * DDIM,
                                   nullptr, dst, 2048, 512, 2);
        tin = t;
    }
}

// round 4
// speedup vs baseline: 2.6732x; 2.6732x over previous
#include <cuda_runtime.h>
#include <cuda_bf16.h>
#include <cstdint>
#include <math.h>

#define BB 16
#define DDIM 512
#define FFF 2048
#define NLAYERS 6
#define MROWS (BB*512)

// ---------------- scratch ----------------
__device__ __align__(256) float g_mem[MROWS*DDIM];
__device__ __align__(256) float g_t  [MROWS*DDIM];
__device__ __align__(256) float g_x  [MROWS*DDIM];
__device__ __align__(256) float g_q  [MROWS*DDIM];
__device__ __align__(256) float g_k  [MROWS*DDIM];
__device__ __align__(256) float g_v  [MROWS*DDIM];
__device__ __align__(256) float g_ao [MROWS*DDIM];
__device__ __align__(256) float g_ff [MROWS*FFF];
// pre-transposed + bf16-split weights: [N][K], K-major
__device__ __align__(256) __nv_bfloat16 g_wh_attn[48*512*512];
__device__ __align__(256) __nv_bfloat16 g_wl_attn[48*512*512];
__device__ __align__(256) __nv_bfloat16 g_wh_ff1 [6*2048*512];
__device__ __align__(256) __nv_bfloat16 g_wl_ff1 [6*2048*512];
__device__ __align__(256) __nv_bfloat16 g_wh_ff2 [6*512*2048];
__device__ __align__(256) __nv_bfloat16 g_wl_ff2 [6*512*2048];
__device__ __align__(256) __nv_bfloat16 g_wh_exp [512*128];
__device__ __align__(256) __nv_bfloat16 g_wl_exp [512*128];

// ---------------- transpose + split: W[K][N] f32 -> Hi/Lo[N][K] bf16 -------
__global__ void tsplit_kernel(const float* __restrict__ W, __nv_bfloat16* __restrict__ Hi,
                              __nv_bfloat16* __restrict__ Lo, int K, int N)
{
    __shared__ float t[32][33];
    const float* Wm = W + (size_t)blockIdx.z*K*N;
    __nv_bfloat16* Hm = Hi + (size_t)blockIdx.z*K*N;
    __nv_bfloat16* Lm = Lo + (size_t)blockIdx.z*K*N;
    int n0 = blockIdx.x*32, k0 = blockIdx.y*32, x = threadIdx.x, y = threadIdx.y;
#pragma unroll
    for (int i = 0; i < 32; i += 8) t[y+i][x] = Wm[(size_t)(k0+y+i)*N + n0+x];
    __syncthreads();
#pragma unroll
    for (int i = 0; i < 32; i += 8) {
        float v = t[x][y+i];
        __nv_bfloat16 h = __float2bfloat16_rn(v);
        Hm[(size_t)(n0+y+i)*K + k0+x] = h;
        Lm[(size_t)(n0+y+i)*K + k0+x] = __float2bfloat16_rn(v - __bfloat162float(h));
    }
}

// ---------------- mma helpers ----------------
__device__ __forceinline__ void mma_bf16(float* d, uint32_t a0, uint32_t a1, uint32_t a2,
                                         uint32_t a3, uint32_t b0, uint32_t b1)
{
    asm volatile(
        "mma.sync.aligned.m16n8k16.row.col.f32.bf16.bf16.f32 "
        "{%0,%1,%2,%3}, {%4,%5,%6,%7}, {%8,%9}, {%0,%1,%2,%3};"
        : "+f"(d[0]), "+f"(d[1]), "+f"(d[2]), "+f"(d[3])
        : "r"(a0), "r"(a1), "r"(a2), "r"(a3), "r"(b0), "r"(b1));
}
__device__ __forceinline__ uint32_t pack2(__nv_bfloat16 a, __nv_bfloat16 b) {
    __nv_bfloat162 h2; h2.x = a; h2.y = b;
    return *(uint32_t*)&h2;
}

// ---------------- GEMM: C = act(A[M,K] @ W + bias (+res)), W via WT hi/lo ----
// BM=128, BN=128, BK=32; 8 warps (2m x 4n), warp tile 64x32; 3xBF16 split.
#define BM 128
#define BN 128
#define BK 32
#define SROW 80                       // smem row stride (bytes), conflict-free
#define REG (128*SROW)                // 10240 B, one operand array
#define STG (4*REG)                   // AH, AL, BH, BL
#define GEMM_SMEM (2*STG)             // 81920

__global__ __launch_bounds__(256)
void tc_gemm(const float* __restrict__ A,
             const __nv_bfloat16* __restrict__ WH, const __nv_bfloat16* __restrict__ WL,
             const float* __restrict__ bias, const float* __restrict__ res,
             float* __restrict__ C, int K, int N, int act)
{
    extern __shared__ char sm[];
    const int tid = threadIdx.x;
    const int lane = tid & 31, wid = tid >> 5;
    const int gid = lane >> 2, tq = lane & 3;
    const int wm = wid & 1, wn = wid >> 1;
    const int m0 = blockIdx.y * BM, n0 = blockIdx.x * BN;
    const float* Ab = A + (size_t)m0 * K;
    const __nv_bfloat16* BHb = WH + (size_t)n0 * K;
    const __nv_bfloat16* BLb = WL + (size_t)n0 * K;
    const int KT = K / BK;

    float4 ra[4];          // A prefetch: 4 chunks (row=ch>>3, k4=(ch&7)*4)
    uint4  rbh[2], rbl[2]; // B prefetch: 2 chunks of 8 bf16 (row=ch>>2, k8=(ch&3)*8)

    auto LOADG = [&](int kt) {
        const float* ap = Ab + kt * BK;
#pragma unroll
        for (int i = 0; i < 4; i++) {
            int ch = tid + i * 256;
            ra[i] = *(const float4*)(ap + (size_t)(ch >> 3) * K + (ch & 7) * 4);
        }
        const __nv_bfloat16* bh = BHb + kt * BK;
        const __nv_bfloat16* bl = BLb + kt * BK;
#pragma unroll
        for (int i = 0; i < 2; i++) {
            int ch = tid + i * 256;
            rbh[i] = *(const uint4*)(bh + (size_t)(ch >> 2) * K + (ch & 3) * 8);
            rbl[i] = *(const uint4*)(bl + (size_t)(ch >> 2) * K + (ch & 3) * 8);
        }
    };
    auto STORES = [&](int s) {
        char* AH = sm + s * STG;
        char* AL = AH + REG;
        char* BH = AH + 2 * REG;
        char* BL = AH + 3 * REG;
#pragma unroll
        for (int i = 0; i < 4; i++) {
            int ch = tid + i * 256;
            int off = (ch >> 3) * SROW + (ch & 7) * 8;   // 4 bf16 = 8B
            __nv_bfloat16 hx = __float2bfloat16_rn(ra[i].x), hy = __float2bfloat16_rn(ra[i].y);
            __nv_bfloat16 hz = __float2bfloat16_rn(ra[i].z), hw = __float2bfloat16_rn(ra[i].w);
            *(uint2*)(AH + off) = make_uint2(pack2(hx, hy), pack2(hz, hw));
            *(uint2*)(AL + off) = make_uint2(
                pack2(__float2bfloat16_rn(ra[i].x - __bfloat162float(hx)),
                      __float2bfloat16_rn(ra[i].y - __bfloat162float(hy))),
                pack2(__float2bfloat16_rn(ra[i].z - __bfloat162float(hz)),
                      __float2bfloat16_rn(ra[i].w - __bfloat162float(hw))));
        }
#pragma unroll
        for (int i = 0; i < 2; i++) {
            int ch = tid + i * 256;
            int off = (ch >> 2) * SROW + (ch & 3) * 16;  // 8 bf16 = 16B -> two 8B stores
            *(uint2*)(BH + off)     = make_uint2(rbh[i].x, rbh[i].y);
            *(uint2*)(BH + off + 8) = make_uint2(rbh[i].z, rbh[i].w);
            *(uint2*)(BL + off)     = make_uint2(rbl[i].x, rbl[i].y);
            *(uint2*)(BL + off + 8) = make_uint2(rbl[i].z, rbl[i].w);
        }
    };

    float acc[4][4][4] = {};
    LOADG(0); STORES(0); __syncthreads();

    for (int kt = 0; kt < KT; kt++) {
        if (kt + 1 < KT) LOADG(kt + 1);
        const char* AH = sm + (kt & 1) * STG;
        const char* AL = AH + REG;
        const char* BH = AH + 2 * REG;
        const char* BL = AH + 3 * REG;
#pragma unroll
        for (int k16 = 0; k16 < 2; k16++) {
            const int kb0 = (k16 * 16 + 2 * tq) * 2;   // byte offset of b32 pair
            uint32_t ah[4][4], al[4][4];
#pragma unroll
            for (int i = 0; i < 4; i++) {
                int r = (wm * 64 + i * 16 + gid) * SROW;
                ah[i][0] = *(const uint32_t*)(AH + r + kb0);
                ah[i][1] = *(const uint32_t*)(AH + r + 8 * SROW + kb0);
                ah[i][2] = *(const uint32_t*)(AH + r + kb0 + 16);
                ah[i][3] = *(const uint32_t*)(AH + r + 8 * SROW + kb0 + 16);
                al[i][0] = *(const uint32_t*)(AL + r + kb0);
                al[i][1] = *(const uint32_t*)(AL + r + 8 * SROW + kb0);
                al[i][2] = *(const uint32_t*)(AL + r + kb0 + 16);
                al[i][3] = *(const uint32_t*)(AL + r + 8 * SROW + kb0 + 16);
            }
#pragma unroll
            for (int j = 0; j < 4; j++) {
                int nr = (wn * 32 + j * 8 + gid) * SROW;
                uint32_t bh0 = *(const uint32_t*)(BH + nr + kb0);
                uint32_t bh1 = *(const uint32_t*)(BH + nr + kb0 + 16);
                uint32_t bl0 = *(const uint32_t*)(BL + nr + kb0);
                uint32_t bl1 = *(const uint32_t*)(BL + nr + kb0 + 16);
#pragma unroll
                for (int i = 0; i < 4; i++) {
                    mma_bf16(acc[i][j], ah[i][0], ah[i][1], ah[i][2], ah[i][3], bh0, bh1);
                    mma_bf16(acc[i][j], ah[i][0], ah[i][1], ah[i][2], ah[i][3], bl0, bl1);
                    mma_bf16(acc[i][j], al[i][0], al[i][1], al[i][2], al[i][3], bh0, bh1);
                }
            }
        }
        if (kt + 1 < KT) STORES((kt + 1) & 1);
        __syncthreads();
    }

    // epilogue
#pragma unroll
    for (int i = 0; i < 4; i++) {
        const int r0 = m0 + wm * 64 + i * 16 + gid;
#pragma unroll
        for (int j = 0; j < 4; j++) {
            const int c = n0 + wn * 32 + j * 8 + 2 * tq;
            float b0 = bias[c], b1 = bias[c + 1];
            float v00 = acc[i][j][0] + b0, v01 = acc[i][j][1] + b1;
            float v10 = acc[i][j][2] + b0, v11 = acc[i][j][3] + b1;
            if (res) {
                const float* rp0 = res + (size_t)r0 * N + c;
                const float* rp1 = res + (size_t)(r0 + 8) * N + c;
                v00 += rp0[0]; v01 += rp0[1]; v10 += rp1[0]; v11 += rp1[1];
            }
            if (act == 1) {
                v00 = v00 > 0.f ? v00 : 0.01f * v00; v01 = v01 > 0.f ? v01 : 0.01f * v01;
                v10 = v10 > 0.f ? v10 : 0.01f * v10; v11 = v11 > 0.f ? v11 : 0.01f * v11;
            } else if (act == 2) {
                v00 = 2.f * (v00 > 0.f ? v00 : 0.01f * v00);
                v01 = 2.f * (v01 > 0.f ? v01 : 0.01f * v01);
                v10 = 2.f * (v10 > 0.f ? v10 : 0.01f * v10);
                v11 = 2.f * (v11 > 0.f ? v11 : 0.01f * v11);
            }
            *(float2*)(C + (size_t)r0 * N + c)       = make_float2(v00, v01);
            *(float2*)(C + (size_t)(r0 + 8) * N + c) = make_float2(v10, v11);
        }
    }
}

// ---------------- LayerNorm (512) ----------------
__global__ void ln_kernel(const float* __restrict__ X, const float* __restrict__ w,
                          const float* __restrict__ b, float* __restrict__ Y)
{
    const int row = blockIdx.x, tid = threadIdx.x;
    float4 v = ((const float4*)(X + (size_t)row*512))[tid];
    float s = v.x+v.y+v.z+v.w, ss = v.x*v.x+v.y*v.y+v.z*v.z+v.w*v.w;
#pragma unroll
    for (int o = 16; o > 0; o >>= 1) { s += __shfl_xor_sync(~0u,s,o); ss += __shfl_xor_sync(~0u,ss,o); }
    __shared__ float rs[4], rss[4];
    int wd = tid>>5, ln = tid&31;
    if (ln == 0) { rs[wd]=s; rss[wd]=ss; }
    __syncthreads();
    s = rs[0]+rs[1]+rs[2]+rs[3]; ss = rss[0]+rss[1]+rss[2]+rss[3];
    float mean = s*(1.f/512.f), var = ss*(1.f/512.f)-mean*mean, inv = rsqrtf(var+1e-5f);
    float4 wv = ((const float4*)w)[tid], bv = ((const float4*)b)[tid], y;
    y.x=(v.x-mean)*inv*wv.x+bv.x; y.y=(v.y-mean)*inv*wv.y+bv.y;
    y.z=(v.z-mean)*inv*wv.z+bv.z; y.w=(v.w-mean)*inv*wv.w+bv.w;
    ((float4*)(Y + (size_t)row*512))[tid] = y;
}

// ---------------- attention: 4x4 register tiled ----------------
#define ALD 68
#define ATT_SMEM (4*64*ALD*4)
__global__ __launch_bounds__(256, 2)
void attn_kernel(const float* __restrict__ Q, const float* __restrict__ K,
                 const float* __restrict__ V, float* __restrict__ O, int causal)
{
    extern __shared__ float smf[];
    float* Qs = smf;                 // [q][d]
    float* Ks = smf + 64*ALD;        // [k][d]
    float* Vs = smf + 2*64*ALD;      // [k][d]
    float* Ps = smf + 3*64*ALD;      // [q][k]
    const int qt = blockIdx.x, bh = blockIdx.y, tid = threadIdx.x;
    const int qg = tid>>4, kg = tid&15;
    const float* Qb = Q + ((size_t)bh*512 + qt*64)*64;
    const float* Kb = K + (size_t)bh*512*64;
    const float* Vb = V + (size_t)bh*512*64;
    float* Ob = O + ((size_t)bh*512 + qt*64)*64;

#pragma unroll
    for (int i = 0; i < 4; i++) {
        int idx = tid + i*256; int r = idx>>4, c = (idx&15)<<2;
        *(float4*)(Qs + r*ALD + c) = *(const float4*)(Qb + r*64 + c);
    }
    float m[4] = {-INFINITY,-INFINITY,-INFINITY,-INFINITY}, lsum[4] = {0,0,0,0};
    float acc[4][4] = {};
    const int ktmax = causal ? qt : 7;

    for (int kt = 0; kt <= ktmax; kt++) {
        __syncthreads();
#pragma unroll
        for (int i = 0; i < 4; i++) {
            int idx = tid + i*256; int r = idx>>4, c = (idx&15)<<2;
            *(float4*)(Ks + r*ALD + c) = *(const float4*)(Kb + (kt*64+r)*64 + c);
            *(float4*)(Vs + r*ALD + c) = *(const float4*)(Vb + (kt*64+r)*64 + c);
        }
        __syncthreads();

        float sc[4][4] = {};
#pragma unroll
        for (int d = 0; d < 64; d += 4) {
            float4 q4[4], k4[4];
#pragma unroll
            for (int a = 0; a < 4; a++) q4[a] = *(const float4*)(Qs + (qg*4+a)*ALD + d);
#pragma unroll
            for (int b = 0; b < 4; b++) k4[b] = *(const float4*)(Ks + (kg*4+b)*ALD + d);
#pragma unroll
            for (int a = 0; a < 4; a++)
#pragma unroll
                for (int b = 0; b < 4; b++) {
                    sc[a][b] = fmaf(q4[a].x, k4[b].x, sc[a][b]);
                    sc[a][b] = fmaf(q4[a].y, k4[b].y, sc[a][b]);
                    sc[a][b] = fmaf(q4[a].z, k4[b].z, sc[a][b]);
                    sc[a][b] = fmaf(q4[a].w, k4[b].w, sc[a][b]);
                }
        }
        float mt[4];
#pragma unroll
        for (int a = 0; a < 4; a++) {
            mt[a] = -INFINITY;
#pragma unroll
            for (int b = 0; b < 4; b++) {
                float s = sc[a][b]*0.03125f;   // /(DH/2) == /32
                if (causal && kt == qt && (kg*4+b) > (qg*4+a)) s = -1e9f;
                sc[a][b] = s; mt[a] = fmaxf(mt[a], s);
            }
        }
#pragma unroll
        for (int o = 1; o < 16; o <<= 1)
#pragma unroll
            for (int a = 0; a < 4; a++) mt[a] = fmaxf(mt[a], __shfl_xor_sync(~0u, mt[a], o));
#pragma unroll
        for (int a = 0; a < 4; a++) {
            float mn = fmaxf(m[a], mt[a]);
            float f = __expf(m[a] - mn);
            m[a] = mn; lsum[a] *= f;
#pragma unroll
            for (int b = 0; b < 4; b++) acc[a][b] *= f;
            float p0 = __expf(sc[a][0]-mn), p1 = __expf(sc[a][1]-mn);
            float p2 = __expf(sc[a][2]-mn), p3 = __expf(sc[a][3]-mn);
            lsum[a] += p0+p1+p2+p3;
            *(float4*)(Ps + (qg*4+a)*ALD + kg*4) = make_float4(p0,p1,p2,p3);
        }
        __syncthreads();

#pragma unroll 4
        for (int k4i = 0; k4i < 16; k4i++) {
            float4 pv[4], vv[4];
#pragma unroll
            for (int a = 0; a < 4; a++) pv[a] = *(const float4*)(Ps + (qg*4+a)*ALD + k4i*4);
#pragma unroll
            for (int j = 0; j < 4; j++) vv[j] = *(const float4*)(Vs + (k4i*4+j)*ALD + kg*4);
#pragma unroll
            for (int a = 0; a < 4; a++) {
                acc[a][0]=fmaf(pv[a].x,vv[0].x,acc[a][0]); acc[a][1]=fmaf(pv[a].x,vv[0].y,acc[a][1]);
                acc[a][2]=fmaf(pv[a].x,vv[0].z,acc[a][2]); acc[a][3]=fmaf(pv[a].x,vv[0].w,acc[a][3]);
                acc[a][0]=fmaf(pv[a].y,vv[1].x,acc[a][0]); acc[a][1]=fmaf(pv[a].y,vv[1].y,acc[a][1]);
                acc[a][2]=fmaf(pv[a].y,vv[1].z,acc[a][2]); acc[a][3]=fmaf(pv[a].y,vv[1].w,acc[a][3]);
                acc[a][0]=fmaf(pv[a].z,vv[2].x,acc[a][0]); acc[a][1]=fmaf(pv[a].z,vv[2].y,acc[a][1]);
                acc[a][2]=fmaf(pv[a].z,vv[2].z,acc[a][2]); acc[a][3]=fmaf(pv[a].z,vv[2].w,acc[a][3]);
                acc[a][0]=fmaf(pv[a].w,vv[3].x,acc[a][0]); acc[a][1]=fmaf(pv[a].w,vv[3].y,acc[a][1]);
                acc[a][2]=fmaf(pv[a].w,vv[3].z,acc[a][2]); acc[a][3]=fmaf(pv[a].w,vv[3].w,acc[a][3]);
            }
        }
    }
#pragma unroll
    for (int o = 1; o < 16; o <<= 1)
#pragma unroll
        for (int a = 0; a < 4; a++) lsum[a] += __shfl_xor_sync(~0u, lsum[a], o);
#pragma unroll
    for (int a = 0; a < 4; a++) {
        float inv = 1.f / lsum[a];
        *(float4*)(Ob + (size_t)(qg*4+a)*64 + kg*4) =
            make_float4(acc[a][0]*inv, acc[a][1]*inv, acc[a][2]*inv, acc[a][3]*inv);
    }
}

// ---------------- orchestration ----------------
extern "C" void kernel_launch(void* const* d_in, const int* in_sizes, int n_in,
                              void* d_out, int out_size)
{
    const float* memory   = (const float*)d_in[0];
    const float* target   = (const float*)d_in[1];
    const float* expand_w = (const float*)d_in[3];
    const float* expand_b = (const float*)d_in[4];
    const float* ln_w     = (const float*)d_in[5];
    const float* ln_b     = (const float*)d_in[6];
    const float* attn_w   = (const float*)d_in[7];
    const float* attn_b   = (const float*)d_in[8];
    const float* ff_w1    = (const float*)d_in[9];
    const float* ff_b1    = (const float*)d_in[10];
    const float* ff_w2    = (const float*)d_in[11];
    const float* ff_b2    = (const float*)d_in[12];
    float* out = (float*)d_out;

    float *mem,*t,*x,*q,*k,*v,*ao,*ff;
    __nv_bfloat16 *whA,*wlA,*wh1,*wl1,*wh2,*wl2,*whe,*wle;
    cudaGetSymbolAddress((void**)&mem, g_mem);
    cudaGetSymbolAddress((void**)&t,   g_t);
    cudaGetSymbolAddress((void**)&x,   g_x);
    cudaGetSymbolAddress((void**)&q,   g_q);
    cudaGetSymbolAddress((void**)&k,   g_k);
    cudaGetSymbolAddress((void**)&v,   g_v);
    cudaGetSymbolAddress((void**)&ao,  g_ao);
    cudaGetSymbolAddress((void**)&ff,  g_ff);
    cudaGetSymbolAddress((void**)&whA, g_wh_attn);
    cudaGetSymbolAddress((void**)&wlA, g_wl_attn);
    cudaGetSymbolAddress((void**)&wh1, g_wh_ff1);
    cudaGetSymbolAddress((void**)&wl1, g_wl_ff1);
    cudaGetSymbolAddress((void**)&wh2, g_wh_ff2);
    cudaGetSymbolAddress((void**)&wl2, g_wl_ff2);
    cudaGetSymbolAddress((void**)&whe, g_wh_exp);
    cudaGetSymbolAddress((void**)&wle, g_wl_exp);

    cudaFuncSetAttribute(tc_gemm,     cudaFuncAttributeMaxDynamicSharedMemorySize, GEMM_SMEM);
    cudaFuncSetAttribute(attn_kernel, cudaFuncAttributeMaxDynamicSharedMemorySize, ATT_SMEM);

    tsplit_kernel<<<dim3(16,16,48), dim3(32,8)>>>(attn_w,   whA, wlA, 512, 512);
    tsplit_kernel<<<dim3(64,16,6),  dim3(32,8)>>>(ff_w1,    wh1, wl1, 512, 2048);
    tsplit_kernel<<<dim3(16,64,6),  dim3(32,8)>>>(ff_w2,    wh2, wl2, 2048, 512);
    tsplit_kernel<<<dim3(16,4,1),   dim3(32,8)>>>(expand_w, whe, wle, 128, 512);

    auto G = [&](const float* A, const __nv_bfloat16* WH, const __nv_bfloat16* WL,
                 const float* bi, const float* rs, float* C, int K, int N, int act) {
        tc_gemm<<<dim3(N/BN, MROWS/BM), 256, GEMM_SMEM>>>(A, WH, WL, bi, rs, C, K, N, act);
    };
    const dim3 ga(8, 128);

    G(memory, whe, wle, expand_b, nullptr, mem, 128, 512, 1);

    const float* tin = target;
    for (int l = 0; l < NLAYERS; l++) {
        const size_t wo = (size_t)l*8*512*512;
        const float* ab = attn_b + (size_t)l*8*DDIM;
        const float* lw = ln_w + (size_t)l*3*DDIM;
        const float* lb = ln_b + (size_t)l*3*DDIM;

        ln_kernel<<<MROWS,128>>>(tin, lw, lb, x);
        G(x, whA+wo+0ull*262144, wlA+wo+0ull*262144, ab+0*DDIM, nullptr, q, 512, 512, 0);
        G(x, whA+wo+1ull*262144, wlA+wo+1ull*262144, ab+1*DDIM, nullptr, k, 512, 512, 0);
        G(x, whA+wo+2ull*262144, wlA+wo+2ull*262144, ab+2*DDIM, nullptr, v, 512, 512, 0);
        attn_kernel<<<ga,256,ATT_SMEM>>>(q, k, v, ao, 1);
        G(ao, whA+wo+3ull*262144, wlA+wo+3ull*262144, ab+3*DDIM, x, t, 512, 512, 0);

        ln_kernel<<<MROWS,128>>>(t, lw+DDIM, lb+DDIM, x);
        G(x,   whA+wo+4ull*262144, wlA+wo+4ull*262144, ab+4*DDIM, nullptr, q, 512, 512, 0);
        G(mem, whA+wo+5ull*262144, wlA+wo+5ull*262144, ab+5*DDIM, nullptr, k, 512, 512, 0);
        G(mem, whA+wo+6ull*262144, wlA+wo+6ull*262144, ab+6*DDIM, nullptr, v, 512, 512, 0);
        attn_kernel<<<ga,256,ATT_SMEM>>>(q, k, v, ao, 0);
        G(ao, whA+wo+7ull*262144, wlA+wo+7ull*262144, ab+7*DDIM, x, t, 512, 512, 0);

        ln_kernel<<<MROWS,128>>>(t, lw+2*DDIM, lb+2*DDIM, x);
        G(x, wh1+(size_t)l*DDIM*FFF, wl1+(size_t)l*DDIM*FFF, ff_b1+(size_t)l*FFF,
          nullptr, ff, 512, 2048, 1);
        float* dst = (l == NLAYERS-1) ? out : t;
        G(ff, wh2+(size_t)l*FFF*DDIM, wl2+(size_t)l*FFF*DDIM, ff_b2+(size_t)l*DDIM,
          nullptr, dst, 2048, 512, 2);
        tin = t;
    }
}

// round 5
// speedup vs baseline: 2.9538x; 1.1050x over previous
#include <cuda_runtime.h>
#include <cuda_bf16.h>
#include <cstdint>
#include <math.h>

#define BB 16
#define DDIM 512
#define FFF 2048
#define NLAYERS 6
#define MROWS (BB*512)

typedef __nv_bfloat16 bf16;
typedef __nv_bfloat162 bf162;

// ---------------- scratch ----------------
__device__ __align__(256) float g_t [MROWS*DDIM];
__device__ __align__(256) float g_x [MROWS*DDIM];
__device__ __align__(256) float g_q [MROWS*DDIM];
__device__ __align__(256) float g_k [MROWS*DDIM];
__device__ __align__(256) float g_v [MROWS*DDIM];
// bf16 hi/lo activation pairs
__device__ __align__(256) bf16 g_xh [MROWS*DDIM];
__device__ __align__(256) bf16 g_xl [MROWS*DDIM];
__device__ __align__(256) bf16 g_aoh[MROWS*DDIM];
__device__ __align__(256) bf16 g_aol[MROWS*DDIM];
__device__ __align__(256) bf16 g_memh[MROWS*DDIM];
__device__ __align__(256) bf16 g_meml[MROWS*DDIM];
__device__ __align__(256) bf16 g_ffh[MROWS*FFF];
__device__ __align__(256) bf16 g_ffl[MROWS*FFF];
__device__ __align__(256) bf16 g_inh[MROWS*128];
__device__ __align__(256) bf16 g_inl[MROWS*128];
// pre-transposed + split weights [N][K]
__device__ __align__(256) bf16 g_wh_attn[48*512*512];
__device__ __align__(256) bf16 g_wl_attn[48*512*512];
__device__ __align__(256) bf16 g_wh_ff1 [6*2048*512];
__device__ __align__(256) bf16 g_wl_ff1 [6*2048*512];
__device__ __align__(256) bf16 g_wh_ff2 [6*512*2048];
__device__ __align__(256) bf16 g_wl_ff2 [6*512*2048];
__device__ __align__(256) bf16 g_wh_exp [512*128];
__device__ __align__(256) bf16 g_wl_exp [512*128];

// ---------------- helpers ----------------
__device__ __forceinline__ uint32_t smem_u32(const void* p){
    uint32_t a; asm("{ .reg .u64 t; cvta.to.shared.u64 t, %1; cvt.u32.u64 %0, t; }":"=r"(a):"l"(p)); return a;
}
__device__ __forceinline__ void ldm_x4(uint32_t* r, uint32_t addr){
    asm volatile("ldmatrix.sync.aligned.m8n8.x4.shared.b16 {%0,%1,%2,%3}, [%4];"
        : "=r"(r[0]),"=r"(r[1]),"=r"(r[2]),"=r"(r[3]) : "r"(addr));
}
__device__ __forceinline__ void cpa16(uint32_t dst, const void* src){
    asm volatile("cp.async.cg.shared.global [%0], [%1], 16;" :: "r"(dst), "l"(src));
}
__device__ __forceinline__ void mma_bf16(float* d, const uint32_t* a, uint32_t b0, uint32_t b1){
    asm volatile(
        "mma.sync.aligned.m16n8k16.row.col.f32.bf16.bf16.f32 "
        "{%0,%1,%2,%3}, {%4,%5,%6,%7}, {%8,%9}, {%0,%1,%2,%3};"
        : "+f"(d[0]), "+f"(d[1]), "+f"(d[2]), "+f"(d[3])
        : "r"(a[0]), "r"(a[1]), "r"(a[2]), "r"(a[3]), "r"(b0), "r"(b1));
}
__device__ __forceinline__ uint32_t pack2(bf16 a, bf16 b){ bf162 h; h.x=a; h.y=b; return *(uint32_t*)&h; }

// ---------------- transpose + split weights ----------------
__global__ void tsplit_kernel(const float* __restrict__ W, bf16* __restrict__ Hi,
                              bf16* __restrict__ Lo, int K, int N)
{
    __shared__ float t[32][33];
    const float* Wm = W + (size_t)blockIdx.z*K*N;
    bf16* Hm = Hi + (size_t)blockIdx.z*K*N;
    bf16* Lm = Lo + (size_t)blockIdx.z*K*N;
    int n0=blockIdx.x*32, k0=blockIdx.y*32, x=threadIdx.x, y=threadIdx.y;
#pragma unroll
    for (int i=0;i<32;i+=8) t[y+i][x] = Wm[(size_t)(k0+y+i)*N + n0+x];
    __syncthreads();
#pragma unroll
    for (int i=0;i<32;i+=8){
        float v = t[x][y+i];
        bf16 h = __float2bfloat16_rn(v);
        Hm[(size_t)(n0+y+i)*K + k0+x] = h;
        Lm[(size_t)(n0+y+i)*K + k0+x] = __float2bfloat16_rn(v - __bfloat162float(h));
    }
}

// ---------------- elementwise split (for memory input) ----------------
__global__ void csplit_kernel(const float* __restrict__ X, bf16* __restrict__ H,
                              bf16* __restrict__ L, int n)
{
    int i = blockIdx.x*blockDim.x + threadIdx.x;
    if (i < n){
        float v = X[i];
        bf16 h = __float2bfloat16_rn(v);
        H[i] = h;
        L[i] = __float2bfloat16_rn(v - __bfloat162float(h));
    }
}

// ---------------- GEMM: 3xBF16 split, cp.async + ldmatrix -------------------
#define BM 128
#define BN 128
#define BK 32
#define SROW 80
#define OPSZ (128*SROW)      // 10240 B
#define STG (4*OPSZ)         // AH AL BH BL = 40960
#define GEMM_SMEM (2*STG)    // 81920

__global__ __launch_bounds__(256)
void tc_gemm(const bf16* __restrict__ AHg, const bf16* __restrict__ ALg,
             const bf16* __restrict__ WH, const bf16* __restrict__ WL,
             const float* __restrict__ bias, const float* __restrict__ res,
             float* __restrict__ Cf, bf16* __restrict__ CH, bf16* __restrict__ CL,
             int K, int N, int act)
{
    extern __shared__ char sm[];
    const uint32_t sbase = smem_u32(sm);
    const int tid = threadIdx.x, lane = tid&31, wid = tid>>5;
    const int gid = lane>>2, tq = lane&3;
    const int wm = wid&1, wn = wid>>1;
    const int m0 = blockIdx.y*BM, n0 = blockIdx.x*BN;
    const bf16* Ah = AHg + (size_t)m0*K;
    const bf16* Al = ALg + (size_t)m0*K;
    const bf16* Bh = WH + (size_t)n0*K;
    const bf16* Bl = WL + (size_t)n0*K;
    const int KT = K/BK;

    const int lrow = tid>>2, lc = tid&3;   // cp.async: 2 chunks/thread/operand
    auto LOAD = [&](int kt){
        uint32_t st = sbase + (kt&1)*STG;
        const bf16* g;
        uint32_t d;
#pragma unroll
        for (int i=0;i<2;i++){
            int row = lrow + i*64;
            uint32_t off = (uint32_t)row*SROW + lc*16;
            size_t go = (size_t)row*K + kt*BK + lc*8;
            g = Ah; d = st;            cpa16(d+off, g+go);
            g = Al; d = st+OPSZ;       cpa16(d+off, g+go);
            g = Bh; d = st+2*OPSZ;     cpa16(d+off, g+go);
            g = Bl; d = st+3*OPSZ;     cpa16(d+off, g+go);
        }
        asm volatile("cp.async.commit_group;" ::: "memory");
    };

    // ldmatrix lane offsets
    const uint32_t aoff = (uint32_t)((wm*64 + (lane&15))*SROW + ((lane>>4)*16));
    const uint32_t boff = (uint32_t)((wn*32 + ((lane>>4)*8) + (lane&7))*SROW + (((lane>>3)&1)*16));

    float acc[4][4][4] = {};
    LOAD(0);
    for (int kt=0; kt<KT; kt++){
        if (kt+1 < KT) LOAD(kt+1);
        if (kt+1 < KT) asm volatile("cp.async.wait_group 1;" ::: "memory");
        else           asm volatile("cp.async.wait_group 0;" ::: "memory");
        __syncthreads();
        const uint32_t st = sbase + (kt&1)*STG;
#pragma unroll
        for (int k16=0; k16<2; k16++){
            const uint32_t ko = k16*32;
            uint32_t ah[4][4], al[4][4], bh[8], bl[8];
#pragma unroll
            for (int i=0;i<4;i++){
                ldm_x4(ah[i], st + aoff + i*16*SROW + ko);
                ldm_x4(al[i], st + OPSZ + aoff + i*16*SROW + ko);
            }
            ldm_x4(bh,   st + 2*OPSZ + boff + ko);
            ldm_x4(bh+4, st + 2*OPSZ + boff + 16*SROW + ko);
            ldm_x4(bl,   st + 3*OPSZ + boff + ko);
            ldm_x4(bl+4, st + 3*OPSZ + boff + 16*SROW + ko);
#pragma unroll
            for (int j=0;j<4;j++){
                uint32_t b0 = bh[2*j], b1 = bh[2*j+1];
                uint32_t c0 = bl[2*j], c1 = bl[2*j+1];
#pragma unroll
                for (int i=0;i<4;i++){
                    mma_bf16(acc[i][j], ah[i], b0, b1);
                    mma_bf16(acc[i][j], ah[i], c0, c1);
                    mma_bf16(acc[i][j], al[i], b0, b1);
                }
            }
        }
        __syncthreads();
    }

    // epilogue
#pragma unroll
    for (int i=0;i<4;i++){
        const int r0 = m0 + wm*64 + i*16 + gid;
#pragma unroll
        for (int j=0;j<4;j++){
            const int c = n0 + wn*32 + j*8 + 2*tq;
            float b0 = bias[c], b1 = bias[c+1];
            float v[4] = {acc[i][j][0]+b0, acc[i][j][1]+b1, acc[i][j][2]+b0, acc[i][j][3]+b1};
            if (res){
                const float* rp0 = res + (size_t)r0*N + c;
                const float* rp1 = res + (size_t)(r0+8)*N + c;
                v[0]+=rp0[0]; v[1]+=rp0[1]; v[2]+=rp1[0]; v[3]+=rp1[1];
            }
            if (act==1){
#pragma unroll
                for (int u=0;u<4;u++) v[u] = v[u]>0.f ? v[u] : 0.01f*v[u];
            } else if (act==2){
#pragma unroll
                for (int u=0;u<4;u++) v[u] = 2.f*(v[u]>0.f ? v[u] : 0.01f*v[u]);
            }
            if (Cf){
                *(float2*)(Cf + (size_t)r0*N + c)     = make_float2(v[0], v[1]);
                *(float2*)(Cf + (size_t)(r0+8)*N + c) = make_float2(v[2], v[3]);
            }
            if (CH){
                bf16 h0=__float2bfloat16_rn(v[0]), h1=__float2bfloat16_rn(v[1]);
                bf16 h2=__float2bfloat16_rn(v[2]), h3=__float2bfloat16_rn(v[3]);
                *(uint32_t*)(CH + (size_t)r0*N + c)     = pack2(h0,h1);
                *(uint32_t*)(CH + (size_t)(r0+8)*N + c) = pack2(h2,h3);
                *(uint32_t*)(CL + (size_t)r0*N + c) =
                    pack2(__float2bfloat16_rn(v[0]-__bfloat162float(h0)),
                          __float2bfloat16_rn(v[1]-__bfloat162float(h1)));
                *(uint32_t*)(CL + (size_t)(r0+8)*N + c) =
                    pack2(__float2bfloat16_rn(v[2]-__bfloat162float(h2)),
                          __float2bfloat16_rn(v[3]-__bfloat162float(h3)));
            }
        }
    }
}

// ---------------- LayerNorm: f32 out + bf16 hi/lo out ----------------
__global__ void ln_kernel(const float* __restrict__ X, const float* __restrict__ w,
                          const float* __restrict__ b, float* __restrict__ Y,
                          bf16* __restrict__ YH, bf16* __restrict__ YL)
{
    const int row = blockIdx.x, tid = threadIdx.x;
    float4 v = ((const float4*)(X + (size_t)row*512))[tid];
    float s = v.x+v.y+v.z+v.w, ss = v.x*v.x+v.y*v.y+v.z*v.z+v.w*v.w;
#pragma unroll
    for (int o=16;o>0;o>>=1){ s+=__shfl_xor_sync(~0u,s,o); ss+=__shfl_xor_sync(~0u,ss,o); }
    __shared__ float rs[4], rss[4];
    int wd=tid>>5, ln=tid&31;
    if (ln==0){ rs[wd]=s; rss[wd]=ss; }
    __syncthreads();
    s=rs[0]+rs[1]+rs[2]+rs[3]; ss=rss[0]+rss[1]+rss[2]+rss[3];
    float mean=s*(1.f/512.f), var=ss*(1.f/512.f)-mean*mean, inv=rsqrtf(var+1e-5f);
    float4 wv=((const float4*)w)[tid], bv=((const float4*)b)[tid], y;
    y.x=(v.x-mean)*inv*wv.x+bv.x; y.y=(v.y-mean)*inv*wv.y+bv.y;
    y.z=(v.z-mean)*inv*wv.z+bv.z; y.w=(v.w-mean)*inv*wv.w+bv.w;
    ((float4*)(Y + (size_t)row*512))[tid] = y;
    bf16 h0=__float2bfloat16_rn(y.x), h1=__float2bfloat16_rn(y.y);
    bf16 h2=__float2bfloat16_rn(y.z), h3=__float2bfloat16_rn(y.w);
    uint32_t* HH = (uint32_t*)(YH + (size_t)row*512);
    uint32_t* LL = (uint32_t*)(YL + (size_t)row*512);
    HH[tid*2]   = pack2(h0,h1);
    HH[tid*2+1] = pack2(h2,h3);
    LL[tid*2]   = pack2(__float2bfloat16_rn(y.x-__bfloat162float(h0)),
                        __float2bfloat16_rn(y.y-__bfloat162float(h1)));
    LL[tid*2+1] = pack2(__float2bfloat16_rn(y.z-__bfloat162float(h2)),
                        __float2bfloat16_rn(y.w-__bfloat162float(h3)));
}

// ---------------- attention: 4x4 register tiled, bf16 pair output ----------
#define ALD 68
#define ATT_SMEM (4*64*ALD*4)
__global__ __launch_bounds__(256, 2)
void attn_kernel(const float* __restrict__ Q, const float* __restrict__ K,
                 const float* __restrict__ V, bf16* __restrict__ OH,
                 bf16* __restrict__ OL, int causal)
{
    extern __shared__ float smf[];
    float* Qs = smf;
    float* Ks = smf + 64*ALD;
    float* Vs = smf + 2*64*ALD;
    float* Ps = smf + 3*64*ALD;
    const int qt = blockIdx.x, bh = blockIdx.y, tid = threadIdx.x;
    const int qg = tid>>4, kg = tid&15;
    const float* Qb = Q + ((size_t)bh*512 + qt*64)*64;
    const float* Kb = K + (size_t)bh*512*64;
    const float* Vb = V + (size_t)bh*512*64;

#pragma unroll
    for (int i=0;i<4;i++){
        int idx=tid+i*256; int r=idx>>4, c=(idx&15)<<2;
        *(float4*)(Qs + r*ALD + c) = *(const float4*)(Qb + r*64 + c);
    }
    float m[4]={-INFINITY,-INFINITY,-INFINITY,-INFINITY}, lsum[4]={0,0,0,0};
    float acc[4][4] = {};
    const int ktmax = causal ? qt : 7;

    for (int kt=0; kt<=ktmax; kt++){
        __syncthreads();
#pragma unroll
        for (int i=0;i<4;i++){
            int idx=tid+i*256; int r=idx>>4, c=(idx&15)<<2;
            *(float4*)(Ks + r*ALD + c) = *(const float4*)(Kb + (kt*64+r)*64 + c);
            *(float4*)(Vs + r*ALD + c) = *(const float4*)(Vb + (kt*64+r)*64 + c);
        }
        __syncthreads();

        float sc[4][4] = {};
#pragma unroll
        for (int d=0; d<64; d+=4){
            float4 q4[4], k4[4];
#pragma unroll
            for (int a=0;a<4;a++) q4[a] = *(const float4*)(Qs + (qg*4+a)*ALD + d);
#pragma unroll
            for (int b=0;b<4;b++) k4[b] = *(const float4*)(Ks + (kg*4+b)*ALD + d);
#pragma unroll
            for (int a=0;a<4;a++)
#pragma unroll
                for (int b=0;b<4;b++){
                    sc[a][b]=fmaf(q4[a].x,k4[b].x,sc[a][b]);
                    sc[a][b]=fmaf(q4[a].y,k4[b].y,sc[a][b]);
                    sc[a][b]=fmaf(q4[a].z,k4[b].z,sc[a][b]);
                    sc[a][b]=fmaf(q4[a].w,k4[b].w,sc[a][b]);
                }
        }
        float mt[4];
#pragma unroll
        for (int a=0;a<4;a++){
            mt[a]=-INFINITY;
#pragma unroll
            for (int b=0;b<4;b++){
                float s = sc[a][b]*0.03125f;
                if (causal && kt==qt && (kg*4+b) > (qg*4+a)) s = -1e9f;
                sc[a][b]=s; mt[a]=fmaxf(mt[a],s);
            }
        }
#pragma unroll
        for (int o=1;o<16;o<<=1)
#pragma unroll
            for (int a=0;a<4;a++) mt[a]=fmaxf(mt[a],__shfl_xor_sync(~0u,mt[a],o));
#pragma unroll
        for (int a=0;a<4;a++){
            float mn=fmaxf(m[a],mt[a]);
            float f=__expf(m[a]-mn);
            m[a]=mn; lsum[a]*=f;
#pragma unroll
            for (int b=0;b<4;b++) acc[a][b]*=f;
            float p0=__expf(sc[a][0]-mn), p1=__expf(sc[a][1]-mn);
            float p2=__expf(sc[a][2]-mn), p3=__expf(sc[a][3]-mn);
            lsum[a]+=p0+p1+p2+p3;
            *(float4*)(Ps + (qg*4+a)*ALD + kg*4) = make_float4(p0,p1,p2,p3);
        }
        __syncthreads();

#pragma unroll 4
        for (int k4i=0;k4i<16;k4i++){
            float4 pv[4], vv[4];
#pragma unroll
            for (int a=0;a<4;a++) pv[a]=*(const float4*)(Ps + (qg*4+a)*ALD + k4i*4);
#pragma unroll
            for (int j=0;j<4;j++) vv[j]=*(const float4*)(Vs + (k4i*4+j)*ALD + kg*4);
#pragma unroll
            for (int a=0;a<4;a++){
                acc[a][0]=fmaf(pv[a].x,vv[0].x,acc[a][0]); acc[a][1]=fmaf(pv[a].x,vv[0].y,acc[a][1]);
                acc[a][2]=fmaf(pv[a].x,vv[0].z,acc[a][2]); acc[a][3]=fmaf(pv[a].x,vv[0].w,acc[a][3]);
                acc[a][0]=fmaf(pv[a].y,vv[1].x,acc[a][0]); acc[a][1]=fmaf(pv[a].y,vv[1].y,acc[a][1]);
                acc[a][2]=fmaf(pv[a].y,vv[1].z,acc[a][2]); acc[a][3]=fmaf(pv[a].y,vv[1].w,acc[a][3]);
                acc[a][0]=fmaf(pv[a].z,vv[2].x,acc[a][0]); acc[a][1]=fmaf(pv[a].z,vv[2].y,acc[a][1]);
                acc[a][2]=fmaf(pv[a].z,vv[2].z,acc[a][2]); acc[a][3]=fmaf(pv[a].z,vv[2].w,acc[a][3]);
                acc[a][0]=fmaf(pv[a].w,vv[3].x,acc[a][0]); acc[a][1]=fmaf(pv[a].w,vv[3].y,acc[a][1]);
                acc[a][2]=fmaf(pv[a].w,vv[3].z,acc[a][2]); acc[a][3]=fmaf(pv[a].w,vv[3].w,acc[a][3]);
            }
        }
    }
#pragma unroll
    for (int o=1;o<16;o<<=1)
#pragma unroll
        for (int a=0;a<4;a++) lsum[a]+=__shfl_xor_sync(~0u,lsum[a],o);
    bf16* OHb = OH + ((size_t)bh*512 + qt*64)*64;
    bf16* OLb = OL + ((size_t)bh*512 + qt*64)*64;
#pragma unroll
    for (int a=0;a<4;a++){
        float inv = 1.f/lsum[a];
        float o0=acc[a][0]*inv, o1=acc[a][1]*inv, o2=acc[a][2]*inv, o3=acc[a][3]*inv;
        bf16 h0=__float2bfloat16_rn(o0), h1=__float2bfloat16_rn(o1);
        bf16 h2=__float2bfloat16_rn(o2), h3=__float2bfloat16_rn(o3);
        size_t off = (size_t)(qg*4+a)*64 + kg*4;
        *(uint32_t*)(OHb+off)   = pack2(h0,h1);
        *(uint32_t*)(OHb+off+2) = pack2(h2,h3);
        *(uint32_t*)(OLb+off)   = pack2(__float2bfloat16_rn(o0-__bfloat162float(h0)),
                                        __float2bfloat16_rn(o1-__bfloat162float(h1)));
        *(uint32_t*)(OLb+off+2) = pack2(__float2bfloat16_rn(o2-__bfloat162float(h2)),
                                        __float2bfloat16_rn(o3-__bfloat162float(h3)));
    }
}

// ---------------- orchestration ----------------
extern "C" void kernel_launch(void* const* d_in, const int* in_sizes, int n_in,
                              void* d_out, int out_size)
{
    const float* memory   = (const float*)d_in[0];
    const float* target   = (const float*)d_in[1];
    const float* expand_w = (const float*)d_in[3];
    const float* expand_b = (const float*)d_in[4];
    const float* ln_w     = (const float*)d_in[5];
    const float* ln_b     = (const float*)d_in[6];
    const float* attn_w   = (const float*)d_in[7];
    const float* attn_b   = (const float*)d_in[8];
    const float* ff_w1    = (const float*)d_in[9];
    const float* ff_b1    = (const float*)d_in[10];
    const float* ff_w2    = (const float*)d_in[11];
    const float* ff_b2    = (const float*)d_in[12];
    float* out = (float*)d_out;

    float *t,*x,*q,*k,*v;
    bf16 *xh,*xl,*aoh,*aol,*memh,*meml,*ffh,*ffl,*inh,*inl;
    bf16 *whA,*wlA,*wh1,*wl1,*wh2,*wl2,*whe,*wle;
    cudaGetSymbolAddress((void**)&t,  g_t);
    cudaGetSymbolAddress((void**)&x,  g_x);
    cudaGetSymbolAddress((void**)&q,  g_q);
    cudaGetSymbolAddress((void**)&k,  g_k);
    cudaGetSymbolAddress((void**)&v,  g_v);
    cudaGetSymbolAddress((void**)&xh, g_xh);
    cudaGetSymbolAddress((void**)&xl, g_xl);
    cudaGetSymbolAddress((void**)&aoh,g_aoh);
    cudaGetSymbolAddress((void**)&aol,g_aol);
    cudaGetSymbolAddress((void**)&memh,g_memh);
    cudaGetSymbolAddress((void**)&meml,g_meml);
    cudaGetSymbolAddress((void**)&ffh,g_ffh);
    cudaGetSymbolAddress((void**)&ffl,g_ffl);
    cudaGetSymbolAddress((void**)&inh,g_inh);
    cudaGetSymbolAddress((void**)&inl,g_inl);
    cudaGetSymbolAddress((void**)&whA,g_wh_attn);
    cudaGetSymbolAddress((void**)&wlA,g_wl_attn);
    cudaGetSymbolAddress((void**)&wh1,g_wh_ff1);
    cudaGetSymbolAddress((void**)&wl1,g_wl_ff1);
    cudaGetSymbolAddress((void**)&wh2,g_wh_ff2);
    cudaGetSymbolAddress((void**)&wl2,g_wl_ff2);
    cudaGetSymbolAddress((void**)&whe,g_wh_exp);
    cudaGetSymbolAddress((void**)&wle,g_wl_exp);

    cudaFuncSetAttribute(tc_gemm,     cudaFuncAttributeMaxDynamicSharedMemorySize, GEMM_SMEM);
    cudaFuncSetAttribute(attn_kernel, cudaFuncAttributeMaxDynamicSharedMemorySize, ATT_SMEM);

    tsplit_kernel<<<dim3(16,16,48), dim3(32,8)>>>(attn_w,   whA, wlA, 512, 512);
    tsplit_kernel<<<dim3(64,16,6),  dim3(32,8)>>>(ff_w1,    wh1, wl1, 512, 2048);
    tsplit_kernel<<<dim3(16,64,6),  dim3(32,8)>>>(ff_w2,    wh2, wl2, 2048, 512);
    tsplit_kernel<<<dim3(16,4,1),   dim3(32,8)>>>(expand_w, whe, wle, 128, 512);
    csplit_kernel<<<MROWS*128/256, 256>>>(memory, inh, inl, MROWS*128);

    auto G = [&](const bf16* AH, const bf16* AL, const bf16* WH, const bf16* WL,
                 const float* bi, const float* rs, float* Cf, bf16* CH, bf16* CL,
                 int K, int N, int act){
        tc_gemm<<<dim3(N/BN, MROWS/BM), 256, GEMM_SMEM>>>(AH, AL, WH, WL, bi, rs, Cf, CH, CL, K, N, act);
    };
    const dim3 ga(8, 128);

    // expand: mem = lrelu(memory @ We + be) -> bf16 pair only
    G(inh, inl, whe, wle, expand_b, nullptr, nullptr, memh, meml, 128, 512, 1);

    const float* tin = target;
    for (int l=0; l<NLAYERS; l++){
        const size_t wo = (size_t)l*8*512*512;
        const float* ab = attn_b + (size_t)l*8*DDIM;
        const float* lw = ln_w + (size_t)l*3*DDIM;
        const float* lb = ln_b + (size_t)l*3*DDIM;

        ln_kernel<<<MROWS,128>>>(tin, lw, lb, x, xh, xl);
        G(xh, xl, whA+wo+0ull*262144, wlA+wo+0ull*262144, ab+0*DDIM, nullptr, q, nullptr, nullptr, 512, 512, 0);
        G(xh, xl, whA+wo+1ull*262144, wlA+wo+1ull*262144, ab+1*DDIM, nullptr, k, nullptr, nullptr, 512, 512, 0);
        G(xh, xl, whA+wo+2ull*262144, wlA+wo+2ull*262144, ab+2*DDIM, nullptr, v, nullptr, nullptr, 512, 512, 0);
        attn_kernel<<<ga,256,ATT_SMEM>>>(q, k, v, aoh, aol, 1);
        G(aoh, aol, whA+wo+3ull*262144, wlA+wo+3ull*262144, ab+3*DDIM, x, t, nullptr, nullptr, 512, 512, 0);

        ln_kernel<<<MROWS,128>>>(t, lw+DDIM, lb+DDIM, x, xh, xl);
        G(xh,   xl,   whA+wo+4ull*262144, wlA+wo+4ull*262144, ab+4*DDIM, nullptr, q, nullptr, nullptr, 512, 512, 0);
        G(memh, meml, whA+wo+5ull*262144, wlA+wo+5ull*262144, ab+5*DDIM, nullptr, k, nullptr, nullptr, 512, 512, 0);
        G(memh, meml, whA+wo+6ull*262144, wlA+wo+6ull*262144, ab+6*DDIM, nullptr, v, nullptr, nullptr, 512, 512, 0);
        attn_kernel<<<ga,256,ATT_SMEM>>>(q, k, v, aoh, aol, 0);
        G(aoh, aol, whA+wo+7ull*262144, wlA+wo+7ull*262144, ab+7*DDIM, x, t, nullptr, nullptr, 512, 512, 0);

        ln_kernel<<<MROWS,128>>>(t, lw+2*DDIM, lb+2*DDIM, x, xh, xl);
        G(xh, xl, wh1+(size_t)l*DDIM*FFF, wl1+(size_t)l*DDIM*FFF, ff_b1+(size_t)l*FFF,
          nullptr, nullptr, ffh, ffl, 512, 2048, 1);
        float* dst = (l==NLAYERS-1) ? out : t;
        G(ffh, ffl, wh2+(size_t)l*FFF*DDIM, wl2+(size_t)l*FFF*DDIM, ff_b2+(size_t)l*DDIM,
          nullptr, dst, nullptr, nullptr, 2048, 512, 2);
        tin = t;
    }
}

// round 8
// speedup vs baseline: 4.4778x; 1.5160x over previous
#include <cuda_runtime.h>
#include <cuda_bf16.h>
#include <cstdint>
#include <math.h>

#define BB 16
#define DDIM 512
#define FFF 2048
#define NLAYERS 6
#define MROWS (BB*512)

typedef __nv_bfloat16 bf16;
typedef __nv_bfloat162 bf162;

// ---------------- scratch ----------------
__device__ __align__(256) float g_t [MROWS*DDIM];
__device__ __align__(256) float g_x [MROWS*DDIM];
__device__ __align__(256) bf16 g_xh [MROWS*DDIM];
__device__ __align__(256) bf16 g_xl [MROWS*DDIM];
__device__ __align__(256) bf16 g_qkvh[MROWS*1536];
__device__ __align__(256) bf16 g_qkvl[MROWS*1536];
__device__ __align__(256) bf16 g_kvh [MROWS*1024];
__device__ __align__(256) bf16 g_kvl [MROWS*1024];
__device__ __align__(256) bf16 g_aoh[MROWS*DDIM];
__device__ __align__(256) bf16 g_aol[MROWS*DDIM];
__device__ __align__(256) bf16 g_memh[MROWS*DDIM];
__device__ __align__(256) bf16 g_meml[MROWS*DDIM];
__device__ __align__(256) bf16 g_ffh[MROWS*FFF];
__device__ __align__(256) bf16 g_ffl[MROWS*FFF];
__device__ __align__(256) bf16 g_inh[MROWS*128];
__device__ __align__(256) bf16 g_inl[MROWS*128];
__device__ __align__(256) bf16 g_wh_attn[48*512*512];
__device__ __align__(256) bf16 g_wl_attn[48*512*512];
__device__ __align__(256) bf16 g_wh_ff1 [6*2048*512];
__device__ __align__(256) bf16 g_wl_ff1 [6*2048*512];
__device__ __align__(256) bf16 g_wh_ff2 [6*512*2048];
__device__ __align__(256) bf16 g_wl_ff2 [6*512*2048];
__device__ __align__(256) bf16 g_wh_exp [512*128];
__device__ __align__(256) bf16 g_wl_exp [512*128];

// ---------------- helpers ----------------
__device__ __forceinline__ uint32_t smem_u32(const void* p){
    uint32_t a; asm("{ .reg .u64 t; cvta.to.shared.u64 t, %1; cvt.u32.u64 %0, t; }":"=r"(a):"l"(p)); return a;
}
__device__ __forceinline__ void ldm_x4(uint32_t* r, uint32_t addr){
    asm volatile("ldmatrix.sync.aligned.m8n8.x4.shared.b16 {%0,%1,%2,%3}, [%4];"
        : "=r"(r[0]),"=r"(r[1]),"=r"(r[2]),"=r"(r[3]) : "r"(addr));
}
__device__ __forceinline__ void ldm_x4t(uint32_t* r, uint32_t addr){
    asm volatile("ldmatrix.sync.aligned.m8n8.x4.trans.shared.b16 {%0,%1,%2,%3}, [%4];"
        : "=r"(r[0]),"=r"(r[1]),"=r"(r[2]),"=r"(r[3]) : "r"(addr));
}
__device__ __forceinline__ void cpa16(uint32_t dst, const void* src){
    asm volatile("cp.async.cg.shared.global [%0], [%1], 16;" :: "r"(dst), "l"(src));
}
__device__ __forceinline__ void mma_bf16(float* d, const uint32_t* a, uint32_t b0, uint32_t b1){
    asm volatile(
        "mma.sync.aligned.m16n8k16.row.col.f32.bf16.bf16.f32 "
        "{%0,%1,%2,%3}, {%4,%5,%6,%7}, {%8,%9}, {%0,%1,%2,%3};"
        : "+f"(d[0]), "+f"(d[1]), "+f"(d[2]), "+f"(d[3])
        : "r"(a[0]), "r"(a[1]), "r"(a[2]), "r"(a[3]), "r"(b0), "r"(b1));
}
__device__ __forceinline__ uint32_t pack2(bf16 a, bf16 b){ bf162 h; h.x=a; h.y=b; return *(uint32_t*)&h; }
__device__ __forceinline__ bf16 bfh(float v){ return __float2bfloat16_rn(v); }
__device__ __forceinline__ float bff(bf16 v){ return __bfloat162float(v); }

// ---------------- transpose + split weights ----------------
__global__ void tsplit_kernel(const float* __restrict__ W, bf16* __restrict__ Hi,
                              bf16* __restrict__ Lo, int K, int N)
{
    __shared__ float t[32][33];
    const float* Wm = W + (size_t)blockIdx.z*K*N;
    bf16* Hm = Hi + (size_t)blockIdx.z*K*N;
    bf16* Lm = Lo + (size_t)blockIdx.z*K*N;
    int n0=blockIdx.x*32, k0=blockIdx.y*32, x=threadIdx.x, y=threadIdx.y;
#pragma unroll
    for (int i=0;i<32;i+=8) t[y+i][x] = Wm[(size_t)(k0+y+i)*N + n0+x];
    __syncthreads();
#pragma unroll
    for (int i=0;i<32;i+=8){
        float v = t[x][y+i];
        bf16 h = bfh(v);
        Hm[(size_t)(n0+y+i)*K + k0+x] = h;
        Lm[(size_t)(n0+y+i)*K + k0+x] = bfh(v - bff(h));
    }
}
__global__ void csplit_kernel(const float* __restrict__ X, bf16* __restrict__ H,
                              bf16* __restrict__ L, int n)
{
    int i = blockIdx.x*blockDim.x + threadIdx.x;
    if (i < n){
        float v = X[i];
        bf16 h = bfh(v);
        H[i] = h; L[i] = bfh(v - bff(h));
    }
}

// ---------------- GEMM (proven core) ----------------
#define BM 128
#define BN 128
#define BK 32
#define SROW 80
#define OPSZ (128*SROW)
#define STG (4*OPSZ)
#define GEMM_SMEM (2*STG)

__global__ __launch_bounds__(256)
void tc_gemm(const bf16* __restrict__ AHg, const bf16* __restrict__ ALg,
             const bf16* __restrict__ WH, const bf16* __restrict__ WL,
             const float* __restrict__ bias, const float* __restrict__ res,
             float* __restrict__ Cf, bf16* __restrict__ CH, bf16* __restrict__ CL,
             int K, int N, int act)
{
    extern __shared__ char sm[];
    const uint32_t sbase = smem_u32(sm);
    const int tid = threadIdx.x, lane = tid&31, wid = tid>>5;
    const int gid = lane>>2, tq = lane&3;
    const int wm = wid&1, wn = wid>>1;
    const int m0 = blockIdx.y*BM, n0 = blockIdx.x*BN;
    const bf16* Ah = AHg + (size_t)m0*K;
    const bf16* Al = ALg + (size_t)m0*K;
    const bf16* Bh = WH + (size_t)n0*K;
    const bf16* Bl = WL + (size_t)n0*K;
    const int KT = K/BK;

    const int lrow = tid>>2, lc = tid&3;
    auto LOAD = [&](int kt){
        uint32_t st = sbase + (kt&1)*STG;
#pragma unroll
        for (int i=0;i<2;i++){
            int row = lrow + i*64;
            uint32_t off = (uint32_t)row*SROW + lc*16;
            size_t go = (size_t)row*K + kt*BK + lc*8;
            cpa16(st+off, Ah+go);
            cpa16(st+OPSZ+off, Al+go);
            cpa16(st+2*OPSZ+off, Bh+go);
            cpa16(st+3*OPSZ+off, Bl+go);
        }
        asm volatile("cp.async.commit_group;" ::: "memory");
    };
    const uint32_t aoff = (uint32_t)((wm*64 + (lane&15))*SROW + ((lane>>4)*16));
    const uint32_t boff = (uint32_t)((wn*32 + ((lane>>4)*8) + (lane&7))*SROW + (((lane>>3)&1)*16));

    float acc[4][4][4] = {};
    LOAD(0);
    for (int kt=0; kt<KT; kt++){
        if (kt+1 < KT) LOAD(kt+1);
        if (kt+1 < KT) asm volatile("cp.async.wait_group 1;" ::: "memory");
        else           asm volatile("cp.async.wait_group 0;" ::: "memory");
        __syncthreads();
        const uint32_t st = sbase + (kt&1)*STG;
#pragma unroll
        for (int k16=0; k16<2; k16++){
            const uint32_t ko = k16*32;
            uint32_t ah[4][4], al[4][4], bh[8], bl[8];
#pragma unroll
            for (int i=0;i<4;i++){
                ldm_x4(ah[i], st + aoff + i*16*SROW + ko);
                ldm_x4(al[i], st + OPSZ + aoff + i*16*SROW + ko);
            }
            ldm_x4(bh,   st + 2*OPSZ + boff + ko);
            ldm_x4(bh+4, st + 2*OPSZ + boff + 16*SROW + ko);
            ldm_x4(bl,   st + 3*OPSZ + boff + ko);
            ldm_x4(bl+4, st + 3*OPSZ + boff + 16*SROW + ko);
#pragma unroll
            for (int j=0;j<4;j++){
                uint32_t b0 = bh[2*j], b1 = bh[2*j+1];
                uint32_t c0 = bl[2*j], c1 = bl[2*j+1];
#pragma unroll
                for (int i=0;i<4;i++){
                    mma_bf16(acc[i][j], ah[i], b0, b1);
                    mma_bf16(acc[i][j], ah[i], c0, c1);
                    mma_bf16(acc[i][j], al[i], b0, b1);
                }
            }
        }
        __syncthreads();
    }
#pragma unroll
    for (int i=0;i<4;i++){
        const int r0 = m0 + wm*64 + i*16 + gid;
#pragma unroll
        for (int j=0;j<4;j++){
            const int c = n0 + wn*32 + j*8 + 2*tq;
            float b0 = bias[c], b1 = bias[c+1];
            float v[4] = {acc[i][j][0]+b0, acc[i][j][1]+b1, acc[i][j][2]+b0, acc[i][j][3]+b1};
            if (res){
                const float* rp0 = res + (size_t)r0*N + c;
                const float* rp1 = res + (size_t)(r0+8)*N + c;
                v[0]+=rp0[0]; v[1]+=rp0[1]; v[2]+=rp1[0]; v[3]+=rp1[1];
            }
            if (act==1){
#pragma unroll
                for (int u=0;u<4;u++) v[u] = v[u]>0.f ? v[u] : 0.01f*v[u];
            } else if (act==2){
#pragma unroll
                for (int u=0;u<4;u++) v[u] = 2.f*(v[u]>0.f ? v[u] : 0.01f*v[u]);
            }
            if (Cf){
                *(float2*)(Cf + (size_t)r0*N + c)     = make_float2(v[0], v[1]);
                *(float2*)(Cf + (size_t)(r0+8)*N + c) = make_float2(v[2], v[3]);
            }
            if (CH){
                bf16 h0=bfh(v[0]), h1=bfh(v[1]), h2=bfh(v[2]), h3=bfh(v[3]);
                *(uint32_t*)(CH + (size_t)r0*N + c)     = pack2(h0,h1);
                *(uint32_t*)(CH + (size_t)(r0+8)*N + c) = pack2(h2,h3);
                *(uint32_t*)(CL + (size_t)r0*N + c) =
                    pack2(bfh(v[0]-bff(h0)), bfh(v[1]-bff(h1)));
                *(uint32_t*)(CL + (size_t)(r0+8)*N + c) =
                    pack2(bfh(v[2]-bff(h2)), bfh(v[3]-bff(h3)));
            }
        }
    }
}

// ---------------- LayerNorm ----------------
__global__ void ln_kernel(const float* __restrict__ X, const float* __restrict__ w,
                          const float* __restrict__ b, float* __restrict__ Y,
                          bf16* __restrict__ YH, bf16* __restrict__ YL)
{
    const int row = blockIdx.x, tid = threadIdx.x;
    float4 v = ((const float4*)(X + (size_t)row*512))[tid];
    float s = v.x+v.y+v.z+v.w, ss = v.x*v.x+v.y*v.y+v.z*v.z+v.w*v.w;
#pragma unroll
    for (int o=16;o>0;o>>=1){ s+=__shfl_xor_sync(~0u,s,o); ss+=__shfl_xor_sync(~0u,ss,o); }
    __shared__ float rs[4], rss[4];
    int wd=tid>>5, ln=tid&31;
    if (ln==0){ rs[wd]=s; rss[wd]=ss; }
    __syncthreads();
    s=rs[0]+rs[1]+rs[2]+rs[3]; ss=rss[0]+rss[1]+rss[2]+rss[3];
    float mean=s*(1.f/512.f), var=ss*(1.f/512.f)-mean*mean, inv=rsqrtf(var+1e-5f);
    float4 wv=((const float4*)w)[tid], bv=((const float4*)b)[tid], y;
    y.x=(v.x-mean)*inv*wv.x+bv.x; y.y=(v.y-mean)*inv*wv.y+bv.y;
    y.z=(v.z-mean)*inv*wv.z+bv.z; y.w=(v.w-mean)*inv*wv.w+bv.w;
    ((float4*)(Y + (size_t)row*512))[tid] = y;
    bf16 h0=bfh(y.x), h1=bfh(y.y), h2=bfh(y.z), h3=bfh(y.w);
    uint32_t* HH = (uint32_t*)(YH + (size_t)row*512);
    uint32_t* LL = (uint32_t*)(YL + (size_t)row*512);
    HH[tid*2]   = pack2(h0,h1);
    HH[tid*2+1] = pack2(h2,h3);
    LL[tid*2]   = pack2(bfh(y.x-bff(h0)), bfh(y.y-bff(h1)));
    LL[tid*2+1] = pack2(bfh(y.z-bff(h2)), bfh(y.w-bff(h3)));
}

// ---------------- tensor-core flash attention (fixed head addressing) -------
// Reference reshape (no transpose): head h, position t, dim dh lives at
//   buffer row  b*512 + h*64 + t/8
//   buffer col  colbase + (t%8)*64 + dh        (colbase folded into pointer)
#define AST 72
#define RSZ (64*AST*2)
#define QSH 0
#define QSL (1*RSZ)
#define KSH (2*RSZ)
#define KSL (3*RSZ)
#define VSH (4*RSZ)
#define VSL (5*RSZ)
#define ATT_SMEM (6*RSZ)

__global__ __launch_bounds__(128)
void attn_mma(const bf16* __restrict__ Qh, const bf16* __restrict__ Ql, int qs,
              const bf16* __restrict__ Kh, const bf16* __restrict__ Kl, int ks,
              const bf16* __restrict__ Vh, const bf16* __restrict__ Vl, int vs,
              bf16* __restrict__ OH, bf16* __restrict__ OL, int causal)
{
    extern __shared__ char smc[];
    const uint32_t sb = smem_u32(smc);
    bf16* smb = (bf16*)smc;
    const int qt = blockIdx.x, bh = blockIdx.y;
    const int b = bh >> 3, h = bh & 7;
    const int tid = threadIdx.x, lane = tid & 31, wid = tid >> 5;
    const int gid = lane >> 2, tq = lane & 3;
    const size_t qrow0 = (size_t)b*512 + h*64 + qt*8;   // base buffer row of Q tile
    const size_t krowb = (size_t)b*512 + h*64;          // + kt*8 per K/V tile

    // load Q tile: smem [query r][dh c]
    for (int i = tid; i < 512; i += 128){
        int r = i >> 3, c = (i & 7) * 8;
        size_t g = (qrow0 + (r>>3))*qs + (r&7)*64 + c;
        *(uint4*)(smb + (QSH/2) + r*AST + c) = *(const uint4*)(Qh + g);
        *(uint4*)(smb + (QSL/2) + r*AST + c) = *(const uint4*)(Ql + g);
    }
    __syncthreads();

    const uint32_t qoff = sb + (uint32_t)(((wid*16 + (lane&15))*AST + (lane>>4)*8)*2);
    const uint32_t koff = sb + (uint32_t)(((((lane>>4)*8) + (lane&7))*AST + ((lane>>3)&1)*8)*2);
    const uint32_t voff = sb + (uint32_t)(((((lane&7) + ((lane>>3)&1)*8)*AST) + (lane>>4)*8)*2);

    uint32_t qfh[4][4], qfl[4][4];
#pragma unroll
    for (int g=0; g<4; g++){
        ldm_x4(qfh[g], qoff + QSH + g*32);
        ldm_x4(qfl[g], qoff + QSL + g*32);
    }

    float m0=-INFINITY, m1=-INFINITY, l0=0.f, l1=0.f;
    float acc[8][4] = {};
    const int ktmax = causal ? qt : 7;

    for (int kt=0; kt<=ktmax; kt++){
        __syncthreads();
        const size_t krow = krowb + kt*8;
        for (int i = tid; i < 512; i += 128){
            int r = i >> 3, c = (i & 7) * 8;
            size_t gk = (krow + (r>>3))*ks + (r&7)*64 + c;
            size_t gv = (krow + (r>>3))*vs + (r&7)*64 + c;
            *(uint4*)(smb + (KSH/2) + r*AST + c) = *(const uint4*)(Kh + gk);
            *(uint4*)(smb + (KSL/2) + r*AST + c) = *(const uint4*)(Kl + gk);
            *(uint4*)(smb + (VSH/2) + r*AST + c) = *(const uint4*)(Vh + gv);
            *(uint4*)(smb + (VSL/2) + r*AST + c) = *(const uint4*)(Vl + gv);
        }
        __syncthreads();

        // S = Q K^T (3-term split)
        float s[8][4] = {};
#pragma unroll
        for (int g=0; g<4; g++){
#pragma unroll
            for (int kk=0; kk<4; kk++){
                uint32_t bk[4], bkl[4];
                ldm_x4(bk,  koff + KSH + g*(16*AST*2) + kk*32);
                ldm_x4(bkl, koff + KSL + g*(16*AST*2) + kk*32);
                mma_bf16(s[2*g],   qfh[kk], bk[0],  bk[1]);
                mma_bf16(s[2*g],   qfh[kk], bkl[0], bkl[1]);
                mma_bf16(s[2*g],   qfl[kk], bk[0],  bk[1]);
                mma_bf16(s[2*g+1], qfh[kk], bk[2],  bk[3]);
                mma_bf16(s[2*g+1], qfh[kk], bkl[2], bkl[3]);
                mma_bf16(s[2*g+1], qfl[kk], bk[2],  bk[3]);
            }
        }

        // scale + causal mask (local reshaped-t indices) + online softmax
        const int rl0 = wid*16 + gid;
        float mx0=-INFINITY, mx1=-INFINITY;
#pragma unroll
        for (int j=0; j<8; j++){
#pragma unroll
            for (int c=0; c<4; c++) s[j][c] *= 0.03125f;
            if (causal && kt == qt){
                int col = j*8 + 2*tq;
                if (col   > rl0)   s[j][0] = -1e9f;
                if (col+1 > rl0)   s[j][1] = -1e9f;
                if (col   > rl0+8) s[j][2] = -1e9f;
                if (col+1 > rl0+8) s[j][3] = -1e9f;
            }
            mx0 = fmaxf(mx0, fmaxf(s[j][0], s[j][1]));
            mx1 = fmaxf(mx1, fmaxf(s[j][2], s[j][3]));
        }
        mx0 = fmaxf(mx0, __shfl_xor_sync(~0u, mx0, 1));
        mx0 = fmaxf(mx0, __shfl_xor_sync(~0u, mx0, 2));
        mx1 = fmaxf(mx1, __shfl_xor_sync(~0u, mx1, 1));
        mx1 = fmaxf(mx1, __shfl_xor_sync(~0u, mx1, 2));
        float mn0 = fmaxf(m0, mx0), mn1 = fmaxf(m1, mx1);
        float f0 = __expf(m0 - mn0), f1 = __expf(m1 - mn1);
        m0 = mn0; m1 = mn1; l0 *= f0; l1 *= f1;
#pragma unroll
        for (int j=0; j<8; j++){
            s[j][0] = __expf(s[j][0]-m0); s[j][1] = __expf(s[j][1]-m0);
            s[j][2] = __expf(s[j][2]-m1); s[j][3] = __expf(s[j][3]-m1);
            l0 += s[j][0] + s[j][1];
            l1 += s[j][2] + s[j][3];
            acc[j][0]*=f0; acc[j][1]*=f0; acc[j][2]*=f1; acc[j][3]*=f1;
        }

        // O += P V  (S-accumulator -> A-fragment identity; trans ldmatrix V)
#pragma unroll
        for (int g=0; g<4; g++){
            float* t0 = s[2*g]; float* t1 = s[2*g+1];
            bf16 h00=bfh(t0[0]), h01=bfh(t0[1]), h02=bfh(t0[2]), h03=bfh(t0[3]);
            bf16 h10=bfh(t1[0]), h11=bfh(t1[1]), h12=bfh(t1[2]), h13=bfh(t1[3]);
            uint32_t aph[4] = { pack2(h00,h01), pack2(h02,h03), pack2(h10,h11), pack2(h12,h13) };
            uint32_t apl[4] = {
                pack2(bfh(t0[0]-bff(h00)), bfh(t0[1]-bff(h01))),
                pack2(bfh(t0[2]-bff(h02)), bfh(t0[3]-bff(h03))),
                pack2(bfh(t1[0]-bff(h10)), bfh(t1[1]-bff(h11))),
                pack2(bfh(t1[2]-bff(h12)), bfh(t1[3]-bff(h13))) };
#pragma unroll
            for (int jj=0; jj<4; jj++){
                uint32_t bv[4], bvl[4];
                ldm_x4t(bv,  voff + VSH + g*(16*AST*2) + jj*32);
                ldm_x4t(bvl, voff + VSL + g*(16*AST*2) + jj*32);
                mma_bf16(acc[2*jj],   aph, bv[0],  bv[1]);
                mma_bf16(acc[2*jj],   aph, bvl[0], bvl[1]);
                mma_bf16(acc[2*jj],   apl, bv[0],  bv[1]);
                mma_bf16(acc[2*jj+1], aph, bv[2],  bv[3]);
                mma_bf16(acc[2*jj+1], aph, bvl[2], bvl[3]);
                mma_bf16(acc[2*jj+1], apl, bv[2],  bv[3]);
            }
        }
    }

    l0 += __shfl_xor_sync(~0u, l0, 1); l0 += __shfl_xor_sync(~0u, l0, 2);
    l1 += __shfl_xor_sync(~0u, l1, 1); l1 += __shfl_xor_sync(~0u, l1, 2);
    float inv0 = 1.f/l0, inv1 = 1.f/l1;
    // output: query q0 = wid*16+gid -> row qrow0 + wid*2, col gid*64 + dh; q0+8 -> row+1
    const size_t orow = qrow0 + wid*2;
#pragma unroll
    for (int j=0; j<8; j++){
        int col = gid*64 + j*8 + 2*tq;
        float o0 = acc[j][0]*inv0, o1 = acc[j][1]*inv0;
        float o2 = acc[j][2]*inv1, o3 = acc[j][3]*inv1;
        bf16 h0=bfh(o0), h1=bfh(o1), h2=bfh(o2), h3=bfh(o3);
        *(uint32_t*)(OH + orow*512 + col)     = pack2(h0,h1);
        *(uint32_t*)(OH + (orow+1)*512 + col) = pack2(h2,h3);
        *(uint32_t*)(OL + orow*512 + col)     = pack2(bfh(o0-bff(h0)), bfh(o1-bff(h1)));
        *(uint32_t*)(OL + (orow+1)*512 + col) = pack2(bfh(o2-bff(h2)), bfh(o3-bff(h3)));
    }
}

// ---------------- orchestration ----------------
extern "C" void kernel_launch(void* const* d_in, const int* in_sizes, int n_in,
                              void* d_out, int out_size)
{
    const float* memory   = (const float*)d_in[0];
    const float* target   = (const float*)d_in[1];
    const float* expand_w = (const float*)d_in[3];
    const float* expand_b = (const float*)d_in[4];
    const float* ln_w     = (const float*)d_in[5];
    const float* ln_b     = (const float*)d_in[6];
    const float* attn_w   = (const float*)d_in[7];
    const float* attn_b   = (const float*)d_in[8];
    const float* ff_w1    = (const float*)d_in[9];
    const float* ff_b1    = (const float*)d_in[10];
    const float* ff_w2    = (const float*)d_in[11];
    const float* ff_b2    = (const float*)d_in[12];
    float* out = (float*)d_out;

    float *t,*x;
    bf16 *xh,*xl,*qkvh,*qkvl,*kvh,*kvl,*aoh,*aol,*memh,*meml,*ffh,*ffl,*inh,*inl;
    bf16 *whA,*wlA,*wh1,*wl1,*wh2,*wl2,*whe,*wle;
    cudaGetSymbolAddress((void**)&t,  g_t);
    cudaGetSymbolAddress((void**)&x,  g_x);
    cudaGetSymbolAddress((void**)&xh, g_xh);
    cudaGetSymbolAddress((void**)&xl, g_xl);
    cudaGetSymbolAddress((void**)&qkvh,g_qkvh);
    cudaGetSymbolAddress((void**)&qkvl,g_qkvl);
    cudaGetSymbolAddress((void**)&kvh,g_kvh);
    cudaGetSymbolAddress((void**)&kvl,g_kvl);
    cudaGetSymbolAddress((void**)&aoh,g_aoh);
    cudaGetSymbolAddress((void**)&aol,g_aol);
    cudaGetSymbolAddress((void**)&memh,g_memh);
    cudaGetSymbolAddress((void**)&meml,g_meml);
    cudaGetSymbolAddress((void**)&ffh,g_ffh);
    cudaGetSymbolAddress((void**)&ffl,g_ffl);
    cudaGetSymbolAddress((void**)&inh,g_inh);
    cudaGetSymbolAddress((void**)&inl,g_inl);
    cudaGetSymbolAddress((void**)&whA,g_wh_attn);
    cudaGetSymbolAddress((void**)&wlA,g_wl_attn);
    cudaGetSymbolAddress((void**)&wh1,g_wh_ff1);
    cudaGetSymbolAddress((void**)&wl1,g_wl_ff1);
    cudaGetSymbolAddress((void**)&wh2,g_wh_ff2);
    cudaGetSymbolAddress((void**)&wl2,g_wl_ff2);
    cudaGetSymbolAddress((void**)&whe,g_wh_exp);
    cudaGetSymbolAddress((void**)&wle,g_wl_exp);

    cudaFuncSetAttribute(tc_gemm,  cudaFuncAttributeMaxDynamicSharedMemorySize, GEMM_SMEM);
    cudaFuncSetAttribute(attn_mma, cudaFuncAttributeMaxDynamicSharedMemorySize, ATT_SMEM);

    tsplit_kernel<<<dim3(16,16,48), dim3(32,8)>>>(attn_w,   whA, wlA, 512, 512);
    tsplit_kernel<<<dim3(64,16,6),  dim3(32,8)>>>(ff_w1,    wh1, wl1, 512, 2048);
    tsplit_kernel<<<dim3(16,64,6),  dim3(32,8)>>>(ff_w2,    wh2, wl2, 2048, 512);
    tsplit_kernel<<<dim3(16,4,1),   dim3(32,8)>>>(expand_w, whe, wle, 128, 512);
    csplit_kernel<<<MROWS*128/256, 256>>>(memory, inh, inl, MROWS*128);

    auto G = [&](const bf16* AH, const bf16* AL, const bf16* WH, const bf16* WL,
                 const float* bi, const float* rs, float* Cf, bf16* CH, bf16* CL,
                 int K, int N, int act){
        tc_gemm<<<dim3(N/BN, MROWS/BM), 256, GEMM_SMEM>>>(AH, AL, WH, WL, bi, rs, Cf, CH, CL, K, N, act);
    };
    const dim3 ga(8, 128);

    // expand: mem (bf16 pair)
    G(inh, inl, whe, wle, expand_b, nullptr, nullptr, memh, meml, 128, 512, 1);

    const float* tin = target;
    for (int l=0; l<NLAYERS; l++){
        const size_t wo = (size_t)l*8*262144;
        const float* ab = attn_b + (size_t)l*8*DDIM;
        const float* lw = ln_w + (size_t)l*3*DDIM;
        const float* lb = ln_b + (size_t)l*3*DDIM;

        // self-attention (fused QKV)
        ln_kernel<<<MROWS,128>>>(tin, lw, lb, x, xh, xl);
        G(xh, xl, whA+wo, wlA+wo, ab, nullptr, nullptr, qkvh, qkvl, 512, 1536, 0);
        attn_mma<<<ga,128,ATT_SMEM>>>(qkvh, qkvl, 1536, qkvh+512, qkvl+512, 1536,
                                      qkvh+1024, qkvl+1024, 1536, aoh, aol, 1);
        G(aoh, aol, whA+wo+3ull*262144, wlA+wo+3ull*262144, ab+3*DDIM, x, t, nullptr, nullptr, 512, 512, 0);

        // cross-attention (fused KV)
        ln_kernel<<<MROWS,128>>>(t, lw+DDIM, lb+DDIM, x, xh, xl);
        G(xh, xl, whA+wo+4ull*262144, wlA+wo+4ull*262144, ab+4*DDIM, nullptr, nullptr, qkvh, qkvl, 512, 512, 0);
        G(memh, meml, whA+wo+5ull*262144, wlA+wo+5ull*262144, ab+5*DDIM, nullptr, nullptr, kvh, kvl, 512, 1024, 0);
        attn_mma<<<ga,128,ATT_SMEM>>>(qkvh, qkvl, 512, kvh, kvl, 1024,
                                      kvh+512, kvl+512, 1024, aoh, aol, 0);
        G(aoh, aol, whA+wo+7ull*262144, wlA+wo+7ull*262144, ab+7*DDIM, x, t, nullptr, nullptr, 512, 512, 0);

        // feed-forward
        ln_kernel<<<MROWS,128>>>(t, lw+2*DDIM, lb+2*DDIM, x, xh, xl);
        G(xh, xl, wh1+(size_t)l*DDIM*FFF, wl1+(size_t)l*DDIM*FFF, ff_b1+(size_t)l*FFF,
          nullptr, nullptr, ffh, ffl, 512, 2048, 1);
        float* dst = (l==NLAYERS-1) ? out : t;
        G(ffh, ffl, wh2+(size_t)l*FFF*DDIM, wl2+(size_t)l*FFF*DDIM, ff_b2+(size_t)l*DDIM,
          nullptr, dst, nullptr, nullptr, 2048, 512, 2);
        tin = t;
    }
}

// round 9
// speedup vs baseline: 4.5109x; 1.0074x over previous
#include <cuda_runtime.h>
#include <cuda_bf16.h>
#include <cstdint>
#include <math.h>

#define BB 16
#define DDIM 512
#define FFF 2048
#define NLAYERS 6
#define MROWS (BB*512)

typedef __nv_bfloat16 bf16;
typedef __nv_bfloat162 bf162;

// ---------------- scratch ----------------
__device__ __align__(256) float g_t [MROWS*DDIM];
__device__ __align__(256) float g_x [MROWS*DDIM];
__device__ __align__(256) bf16 g_xh [MROWS*DDIM];
__device__ __align__(256) bf16 g_xl [MROWS*DDIM];
__device__ __align__(256) bf16 g_qkvh[MROWS*1536];
__device__ __align__(256) bf16 g_qkvl[MROWS*1536];
__device__ __align__(256) bf16 g_kvh [MROWS*1024];
__device__ __align__(256) bf16 g_kvl [MROWS*1024];
__device__ __align__(256) bf16 g_aoh[MROWS*DDIM];
__device__ __align__(256) bf16 g_aol[MROWS*DDIM];
__device__ __align__(256) bf16 g_memh[MROWS*DDIM];
__device__ __align__(256) bf16 g_meml[MROWS*DDIM];
__device__ __align__(256) bf16 g_ffh[MROWS*FFF];
__device__ __align__(256) bf16 g_ffl[MROWS*FFF];
__device__ __align__(256) bf16 g_inh[MROWS*128];
__device__ __align__(256) bf16 g_inl[MROWS*128];
__device__ __align__(256) bf16 g_wh_attn[48*512*512];
__device__ __align__(256) bf16 g_wl_attn[48*512*512];
__device__ __align__(256) bf16 g_wh_ff1 [6*2048*512];
__device__ __align__(256) bf16 g_wl_ff1 [6*2048*512];
__device__ __align__(256) bf16 g_wh_ff2 [6*512*2048];
__device__ __align__(256) bf16 g_wl_ff2 [6*512*2048];
__device__ __align__(256) bf16 g_wh_exp [512*128];
__device__ __align__(256) bf16 g_wl_exp [512*128];

// ---------------- helpers ----------------
__device__ __forceinline__ uint32_t smem_u32(const void* p){
    uint32_t a; asm("{ .reg .u64 t; cvta.to.shared.u64 t, %1; cvt.u32.u64 %0, t; }":"=r"(a):"l"(p)); return a;
}
__device__ __forceinline__ void ldm_x4(uint32_t* r, uint32_t addr){
    asm volatile("ldmatrix.sync.aligned.m8n8.x4.shared.b16 {%0,%1,%2,%3}, [%4];"
        : "=r"(r[0]),"=r"(r[1]),"=r"(r[2]),"=r"(r[3]) : "r"(addr));
}
__device__ __forceinline__ void ldm_x4t(uint32_t* r, uint32_t addr){
    asm volatile("ldmatrix.sync.aligned.m8n8.x4.trans.shared.b16 {%0,%1,%2,%3}, [%4];"
        : "=r"(r[0]),"=r"(r[1]),"=r"(r[2]),"=r"(r[3]) : "r"(addr));
}
__device__ __forceinline__ void cpa16(uint32_t dst, const void* src){
    asm volatile("cp.async.cg.shared.global [%0], [%1], 16;" :: "r"(dst), "l"(src));
}
__device__ __forceinline__ void mma_bf16(float* d, const uint32_t* a, uint32_t b0, uint32_t b1){
    asm volatile(
        "mma.sync.aligned.m16n8k16.row.col.f32.bf16.bf16.f32 "
        "{%0,%1,%2,%3}, {%4,%5,%6,%7}, {%8,%9}, {%0,%1,%2,%3};"
        : "+f"(d[0]), "+f"(d[1]), "+f"(d[2]), "+f"(d[3])
        : "r"(a[0]), "r"(a[1]), "r"(a[2]), "r"(a[3]), "r"(b0), "r"(b1));
}
__device__ __forceinline__ uint32_t pack2(bf16 a, bf16 b){ bf162 h; h.x=a; h.y=b; return *(uint32_t*)&h; }
__device__ __forceinline__ bf16 bfh(float v){ return __float2bfloat16_rn(v); }
__device__ __forceinline__ float bff(bf16 v){ return __bfloat162float(v); }

// ---------------- transpose + split weights ----------------
__global__ void tsplit_kernel(const float* __restrict__ W, bf16* __restrict__ Hi,
                              bf16* __restrict__ Lo, int K, int N)
{
    __shared__ float t[32][33];
    const float* Wm = W + (size_t)blockIdx.z*K*N;
    bf16* Hm = Hi + (size_t)blockIdx.z*K*N;
    bf16* Lm = Lo + (size_t)blockIdx.z*K*N;
    int n0=blockIdx.x*32, k0=blockIdx.y*32, x=threadIdx.x, y=threadIdx.y;
#pragma unroll
    for (int i=0;i<32;i+=8) t[y+i][x] = Wm[(size_t)(k0+y+i)*N + n0+x];
    __syncthreads();
#pragma unroll
    for (int i=0;i<32;i+=8){
        float v = t[x][y+i];
        bf16 h = bfh(v);
        Hm[(size_t)(n0+y+i)*K + k0+x] = h;
        Lm[(size_t)(n0+y+i)*K + k0+x] = bfh(v - bff(h));
    }
}
__global__ void csplit_kernel(const float* __restrict__ X, bf16* __restrict__ H,
                              bf16* __restrict__ L, int n)
{
    int i = blockIdx.x*blockDim.x + threadIdx.x;
    if (i < n){
        float v = X[i];
        bf16 h = bfh(v);
        H[i] = h; L[i] = bfh(v - bff(h));
    }
}

// ---------------- GEMM (proven core; now 2 CTAs/SM) ----------------
#define BM 128
#define BN 128
#define BK 32
#define SROW 80
#define OPSZ (128*SROW)
#define STG (4*OPSZ)
#define GEMM_SMEM (2*STG)

__global__ __launch_bounds__(256, 2)
void tc_gemm(const bf16* __restrict__ AHg, const bf16* __restrict__ ALg,
             const bf16* __restrict__ WH, const bf16* __restrict__ WL,
             const float* __restrict__ bias, const float* __restrict__ res,
             float* __restrict__ Cf, bf16* __restrict__ CH, bf16* __restrict__ CL,
             int K, int N, int act)
{
    extern __shared__ char sm[];
    const uint32_t sbase = smem_u32(sm);
    const int tid = threadIdx.x, lane = tid&31, wid = tid>>5;
    const int gid = lane>>2, tq = lane&3;
    const int wm = wid&1, wn = wid>>1;
    const int m0 = blockIdx.y*BM, n0 = blockIdx.x*BN;
    const bf16* Ah = AHg + (size_t)m0*K;
    const bf16* Al = ALg + (size_t)m0*K;
    const bf16* Bh = WH + (size_t)n0*K;
    const bf16* Bl = WL + (size_t)n0*K;
    const int KT = K/BK;

    const int lrow = tid>>2, lc = tid&3;
    auto LOAD = [&](int kt){
        uint32_t st = sbase + (kt&1)*STG;
#pragma unroll
        for (int i=0;i<2;i++){
            int row = lrow + i*64;
            uint32_t off = (uint32_t)row*SROW + lc*16;
            size_t go = (size_t)row*K + kt*BK + lc*8;
            cpa16(st+off, Ah+go);
            cpa16(st+OPSZ+off, Al+go);
            cpa16(st+2*OPSZ+off, Bh+go);
            cpa16(st+3*OPSZ+off, Bl+go);
        }
        asm volatile("cp.async.commit_group;" ::: "memory");
    };
    const uint32_t aoff = (uint32_t)((wm*64 + (lane&15))*SROW + ((lane>>4)*16));
    const uint32_t boff = (uint32_t)((wn*32 + ((lane>>4)*8) + (lane&7))*SROW + (((lane>>3)&1)*16));

    float acc[4][4][4] = {};
    LOAD(0);
    for (int kt=0; kt<KT; kt++){
        if (kt+1 < KT) LOAD(kt+1);
        if (kt+1 < KT) asm volatile("cp.async.wait_group 1;" ::: "memory");
        else           asm volatile("cp.async.wait_group 0;" ::: "memory");
        __syncthreads();
        const uint32_t st = sbase + (kt&1)*STG;
#pragma unroll
        for (int k16=0; k16<2; k16++){
            const uint32_t ko = k16*32;
            uint32_t ah[4][4], al[4][4], bh[8], bl[8];
#pragma unroll
            for (int i=0;i<4;i++){
                ldm_x4(ah[i], st + aoff + i*16*SROW + ko);
                ldm_x4(al[i], st + OPSZ + aoff + i*16*SROW + ko);
            }
            ldm_x4(bh,   st + 2*OPSZ + boff + ko);
            ldm_x4(bh+4, st + 2*OPSZ + boff + 16*SROW + ko);
            ldm_x4(bl,   st + 3*OPSZ + boff + ko);
            ldm_x4(bl+4, st + 3*OPSZ + boff + 16*SROW + ko);
#pragma unroll
            for (int j=0;j<4;j++){
                uint32_t b0 = bh[2*j], b1 = bh[2*j+1];
                uint32_t c0 = bl[2*j], c1 = bl[2*j+1];
#pragma unroll
                for (int i=0;i<4;i++){
                    mma_bf16(acc[i][j], ah[i], b0, b1);
                    mma_bf16(acc[i][j], ah[i], c0, c1);
                    mma_bf16(acc[i][j], al[i], b0, b1);
                }
            }
        }
        __syncthreads();
    }
#pragma unroll
    for (int i=0;i<4;i++){
        const int r0 = m0 + wm*64 + i*16 + gid;
#pragma unroll
        for (int j=0;j<4;j++){
            const int c = n0 + wn*32 + j*8 + 2*tq;
            float b0 = bias[c], b1 = bias[c+1];
            float v[4] = {acc[i][j][0]+b0, acc[i][j][1]+b1, acc[i][j][2]+b0, acc[i][j][3]+b1};
            if (res){
                const float* rp0 = res + (size_t)r0*N + c;
                const float* rp1 = res + (size_t)(r0+8)*N + c;
                v[0]+=rp0[0]; v[1]+=rp0[1]; v[2]+=rp1[0]; v[3]+=rp1[1];
            }
            if (act==1){
#pragma unroll
                for (int u=0;u<4;u++) v[u] = v[u]>0.f ? v[u] : 0.01f*v[u];
            } else if (act==2){
#pragma unroll
                for (int u=0;u<4;u++) v[u] = 2.f*(v[u]>0.f ? v[u] : 0.01f*v[u]);
            }
            if (Cf){
                *(float2*)(Cf + (size_t)r0*N + c)     = make_float2(v[0], v[1]);
                *(float2*)(Cf + (size_t)(r0+8)*N + c) = make_float2(v[2], v[3]);
            }
            if (CH){
                bf16 h0=bfh(v[0]), h1=bfh(v[1]), h2=bfh(v[2]), h3=bfh(v[3]);
                *(uint32_t*)(CH + (size_t)r0*N + c)     = pack2(h0,h1);
                *(uint32_t*)(CH + (size_t)(r0+8)*N + c) = pack2(h2,h3);
                *(uint32_t*)(CL + (size_t)r0*N + c) =
                    pack2(bfh(v[0]-bff(h0)), bfh(v[1]-bff(h1)));
                *(uint32_t*)(CL + (size_t)(r0+8)*N + c) =
                    pack2(bfh(v[2]-bff(h2)), bfh(v[3]-bff(h3)));
            }
        }
    }
}

// ---------------- LayerNorm ----------------
__global__ void ln_kernel(const float* __restrict__ X, const float* __restrict__ w,
                          const float* __restrict__ b, float* __restrict__ Y,
                          bf16* __restrict__ YH, bf16* __restrict__ YL)
{
    const int row = blockIdx.x, tid = threadIdx.x;
    float4 v = ((const float4*)(X + (size_t)row*512))[tid];
    float s = v.x+v.y+v.z+v.w, ss = v.x*v.x+v.y*v.y+v.z*v.z+v.w*v.w;
#pragma unroll
    for (int o=16;o>0;o>>=1){ s+=__shfl_xor_sync(~0u,s,o); ss+=__shfl_xor_sync(~0u,ss,o); }
    __shared__ float rs[4], rss[4];
    int wd=tid>>5, ln=tid&31;
    if (ln==0){ rs[wd]=s; rss[wd]=ss; }
    __syncthreads();
    s=rs[0]+rs[1]+rs[2]+rs[3]; ss=rss[0]+rss[1]+rss[2]+rss[3];
    float mean=s*(1.f/512.f), var=ss*(1.f/512.f)-mean*mean, inv=rsqrtf(var+1e-5f);
    float4 wv=((const float4*)w)[tid], bv=((const float4*)b)[tid], y;
    y.x=(v.x-mean)*inv*wv.x+bv.x; y.y=(v.y-mean)*inv*wv.y+bv.y;
    y.z=(v.z-mean)*inv*wv.z+bv.z; y.w=(v.w-mean)*inv*wv.w+bv.w;
    ((float4*)(Y + (size_t)row*512))[tid] = y;
    bf16 h0=bfh(y.x), h1=bfh(y.y), h2=bfh(y.z), h3=bfh(y.w);
    uint32_t* HH = (uint32_t*)(YH + (size_t)row*512);
    uint32_t* LL = (uint32_t*)(YL + (size_t)row*512);
    HH[tid*2]   = pack2(h0,h1);
    HH[tid*2+1] = pack2(h2,h3);
    LL[tid*2]   = pack2(bfh(y.x-bff(h0)), bfh(y.y-bff(h1)));
    LL[tid*2+1] = pack2(bfh(y.z-bff(h2)), bfh(y.w-bff(h3)));
}

// ---------------- tensor-core flash attention (proven, fixed addressing) ----
#define AST 72
#define RSZ (64*AST*2)
#define QSH 0
#define QSL (1*RSZ)
#define KSH (2*RSZ)
#define KSL (3*RSZ)
#define VSH (4*RSZ)
#define VSL (5*RSZ)
#define ATT_SMEM (6*RSZ)

__global__ __launch_bounds__(128)
void attn_mma(const bf16* __restrict__ Qh, const bf16* __restrict__ Ql, int qs,
              const bf16* __restrict__ Kh, const bf16* __restrict__ Kl, int ks,
              const bf16* __restrict__ Vh, const bf16* __restrict__ Vl, int vs,
              bf16* __restrict__ OH, bf16* __restrict__ OL, int causal)
{
    extern __shared__ char smc[];
    const uint32_t sb = smem_u32(smc);
    bf16* smb = (bf16*)smc;
    const int qt = blockIdx.x, bh = blockIdx.y;
    const int b = bh >> 3, h = bh & 7;
    const int tid = threadIdx.x, lane = tid & 31, wid = tid >> 5;
    const int gid = lane >> 2, tq = lane & 3;
    const size_t qrow0 = (size_t)b*512 + h*64 + qt*8;
    const size_t krowb = (size_t)b*512 + h*64;

    for (int i = tid; i < 512; i += 128){
        int r = i >> 3, c = (i & 7) * 8;
        size_t g = (qrow0 + (r>>3))*qs + (r&7)*64 + c;
        *(uint4*)(smb + (QSH/2) + r*AST + c) = *(const uint4*)(Qh + g);
        *(uint4*)(smb + (QSL/2) + r*AST + c) = *(const uint4*)(Ql + g);
    }
    __syncthreads();

    const uint32_t qoff = sb + (uint32_t)(((wid*16 + (lane&15))*AST + (lane>>4)*8)*2);
    const uint32_t koff = sb + (uint32_t)(((((lane>>4)*8) + (lane&7))*AST + ((lane>>3)&1)*8)*2);
    const uint32_t voff = sb + (uint32_t)(((((lane&7) + ((lane>>3)&1)*8)*AST) + (lane>>4)*8)*2);

    uint32_t qfh[4][4], qfl[4][4];
#pragma unroll
    for (int g=0; g<4; g++){
        ldm_x4(qfh[g], qoff + QSH + g*32);
        ldm_x4(qfl[g], qoff + QSL + g*32);
    }

    float m0=-INFINITY, m1=-INFINITY, l0=0.f, l1=0.f;
    float acc[8][4] = {};
    const int ktmax = causal ? qt : 7;

    for (int kt=0; kt<=ktmax; kt++){
        __syncthreads();
        const size_t krow = krowb + kt*8;
        for (int i = tid; i < 512; i += 128){
            int r = i >> 3, c = (i & 7) * 8;
            size_t gk = (krow + (r>>3))*ks + (r&7)*64 + c;
            size_t gv = (krow + (r>>3))*vs + (r&7)*64 + c;
            *(uint4*)(smb + (KSH/2) + r*AST + c) = *(const uint4*)(Kh + gk);
            *(uint4*)(smb + (KSL/2) + r*AST + c) = *(const uint4*)(Kl + gk);
            *(uint4*)(smb + (VSH/2) + r*AST + c) = *(const uint4*)(Vh + gv);
            *(uint4*)(smb + (VSL/2) + r*AST + c) = *(const uint4*)(Vl + gv);
        }
        __syncthreads();

        float s[8][4] = {};
#pragma unroll
        for (int g=0; g<4; g++){
#pragma unroll
            for (int kk=0; kk<4; kk++){
                uint32_t bk[4], bkl[4];
                ldm_x4(bk,  koff + KSH + g*(16*AST*2) + kk*32);
                ldm_x4(bkl, koff + KSL + g*(16*AST*2) + kk*32);
                mma_bf16(s[2*g],   qfh[kk], bk[0],  bk[1]);
                mma_bf16(s[2*g],   qfh[kk], bkl[0], bkl[1]);
                mma_bf16(s[2*g],   qfl[kk], bk[0],  bk[1]);
                mma_bf16(s[2*g+1], qfh[kk], bk[2],  bk[3]);
                mma_bf16(s[2*g+1], qfh[kk], bkl[2], bkl[3]);
                mma_bf16(s[2*g+1], qfl[kk], bk[2],  bk[3]);
            }
        }

        const int rl0 = wid*16 + gid;
        float mx0=-INFINITY, mx1=-INFINITY;
#pragma unroll
        for (int j=0; j<8; j++){
#pragma unroll
            for (int c=0; c<4; c++) s[j][c] *= 0.03125f;
            if (causal && kt == qt){
                int col = j*8 + 2*tq;
                if (col   > rl0)   s[j][0] = -1e9f;
                if (col+1 > rl0)   s[j][1] = -1e9f;
                if (col   > rl0+8) s[j][2] = -1e9f;
                if (col+1 > rl0+8) s[j][3] = -1e9f;
            }
            mx0 = fmaxf(mx0, fmaxf(s[j][0], s[j][1]));
            mx1 = fmaxf(mx1, fmaxf(s[j][2], s[j][3]));
        }
        mx0 = fmaxf(mx0, __shfl_xor_sync(~0u, mx0, 1));
        mx0 = fmaxf(mx0, __shfl_xor_sync(~0u, mx0, 2));
        mx1 = fmaxf(mx1, __shfl_xor_sync(~0u, mx1, 1));
        mx1 = fmaxf(mx1, __shfl_xor_sync(~0u, mx1, 2));
        float mn0 = fmaxf(m0, mx0), mn1 = fmaxf(m1, mx1);
        float f0 = __expf(m0 - mn0), f1 = __expf(m1 - mn1);
        m0 = mn0; m1 = mn1; l0 *= f0; l1 *= f1;
#pragma unroll
        for (int j=0; j<8; j++){
            s[j][0] = __expf(s[j][0]-m0); s[j][1] = __expf(s[j][1]-m0);
            s[j][2] = __expf(s[j][2]-m1); s[j][3] = __expf(s[j][3]-m1);
            l0 += s[j][0] + s[j][1];
            l1 += s[j][2] + s[j][3];
            acc[j][0]*=f0; acc[j][1]*=f0; acc[j][2]*=f1; acc[j][3]*=f1;
        }

#pragma unroll
        for (int g=0; g<4; g++){
            float* t0 = s[2*g]; float* t1 = s[2*g+1];
            bf16 h00=bfh(t0[0]), h01=bfh(t0[1]), h02=bfh(t0[2]), h03=bfh(t0[3]);
            bf16 h10=bfh(t1[0]), h11=bfh(t1[1]), h12=bfh(t1[2]), h13=bfh(t1[3]);
            uint32_t aph[4] = { pack2(h00,h01), pack2(h02,h03), pack2(h10,h11), pack2(h12,h13) };
            uint32_t apl[4] = {
                pack2(bfh(t0[0]-bff(h00)), bfh(t0[1]-bff(h01))),
                pack2(bfh(t0[2]-bff(h02)), bfh(t0[3]-bff(h03))),
                pack2(bfh(t1[0]-bff(h10)), bfh(t1[1]-bff(h11))),
                pack2(bfh(t1[2]-bff(h12)), bfh(t1[3]-bff(h13))) };
#pragma unroll
            for (int jj=0; jj<4; jj++){
                uint32_t bv[4], bvl[4];
                ldm_x4t(bv,  voff + VSH + g*(16*AST*2) + jj*32);
                ldm_x4t(bvl, voff + VSL + g*(16*AST*2) + jj*32);
                mma_bf16(acc[2*jj],   aph, bv[0],  bv[1]);
                mma_bf16(acc[2*jj],   aph, bvl[0], bvl[1]);
                mma_bf16(acc[2*jj],   apl, bv[0],  bv[1]);
                mma_bf16(acc[2*jj+1], aph, bv[2],  bv[3]);
                mma_bf16(acc[2*jj+1], aph, bvl[2], bvl[3]);
                mma_bf16(acc[2*jj+1], apl, bv[2],  bv[3]);
            }
        }
    }

    l0 += __shfl_xor_sync(~0u, l0, 1); l0 += __shfl_xor_sync(~0u, l0, 2);
    l1 += __shfl_xor_sync(~0u, l1, 1); l1 += __shfl_xor_sync(~0u, l1, 2);
    float inv0 = 1.f/l0, inv1 = 1.f/l1;
    const size_t orow = qrow0 + wid*2;
#pragma unroll
    for (int j=0; j<8; j++){
        int col = gid*64 + j*8 + 2*tq;
        float o0 = acc[j][0]*inv0, o1 = acc[j][1]*inv0;
        float o2 = acc[j][2]*inv1, o3 = acc[j][3]*inv1;
        bf16 h0=bfh(o0), h1=bfh(o1), h2=bfh(o2), h3=bfh(o3);
        *(uint32_t*)(OH + orow*512 + col)     = pack2(h0,h1);
        *(uint32_t*)(OH + (orow+1)*512 + col) = pack2(h2,h3);
        *(uint32_t*)(OL + orow*512 + col)     = pack2(bfh(o0-bff(h0)), bfh(o1-bff(h1)));
        *(uint32_t*)(OL + (orow+1)*512 + col) = pack2(bfh(o2-bff(h2)), bfh(o3-bff(h3)));
    }
}

// ---------------- orchestration ----------------
extern "C" void kernel_launch(void* const* d_in, const int* in_sizes, int n_in,
                              void* d_out, int out_size)
{
    const float* memory   = (const float*)d_in[0];
    const float* target   = (const float*)d_in[1];
    const float* expand_w = (const float*)d_in[3];
    const float* expand_b = (const float*)d_in[4];
    const float* ln_w     = (const float*)d_in[5];
    const float* ln_b     = (const float*)d_in[6];
    const float* attn_w   = (const float*)d_in[7];
    const float* attn_b   = (const float*)d_in[8];
    const float* ff_w1    = (const float*)d_in[9];
    const float* ff_b1    = (const float*)d_in[10];
    const float* ff_w2    = (const float*)d_in[11];
    const float* ff_b2    = (const float*)d_in[12];
    float* out = (float*)d_out;

    float *t,*x;
    bf16 *xh,*xl,*qkvh,*qkvl,*kvh,*kvl,*aoh,*aol,*memh,*meml,*ffh,*ffl,*inh,*inl;
    bf16 *whA,*wlA,*wh1,*wl1,*wh2,*wl2,*whe,*wle;
    cudaGetSymbolAddress((void**)&t,  g_t);
    cudaGetSymbolAddress((void**)&x,  g_x);
    cudaGetSymbolAddress((void**)&xh, g_xh);
    cudaGetSymbolAddress((void**)&xl, g_xl);
    cudaGetSymbolAddress((void**)&qkvh,g_qkvh);
    cudaGetSymbolAddress((void**)&qkvl,g_qkvl);
    cudaGetSymbolAddress((void**)&kvh,g_kvh);
    cudaGetSymbolAddress((void**)&kvl,g_kvl);
    cudaGetSymbolAddress((void**)&aoh,g_aoh);
    cudaGetSymbolAddress((void**)&aol,g_aol);
    cudaGetSymbolAddress((void**)&memh,g_memh);
    cudaGetSymbolAddress((void**)&meml,g_meml);
    cudaGetSymbolAddress((void**)&ffh,g_ffh);
    cudaGetSymbolAddress((void**)&ffl,g_ffl);
    cudaGetSymbolAddress((void**)&inh,g_inh);
    cudaGetSymbolAddress((void**)&inl,g_inl);
    cudaGetSymbolAddress((void**)&whA,g_wh_attn);
    cudaGetSymbolAddress((void**)&wlA,g_wl_attn);
    cudaGetSymbolAddress((void**)&wh1,g_wh_ff1);
    cudaGetSymbolAddress((void**)&wl1,g_wl_ff1);
    cudaGetSymbolAddress((void**)&wh2,g_wh_ff2);
    cudaGetSymbolAddress((void**)&wl2,g_wl_ff2);
    cudaGetSymbolAddress((void**)&whe,g_wh_exp);
    cudaGetSymbolAddress((void**)&wle,g_wl_exp);

    cudaFuncSetAttribute(tc_gemm,  cudaFuncAttributeMaxDynamicSharedMemorySize, GEMM_SMEM);
    cudaFuncSetAttribute(attn_mma, cudaFuncAttributeMaxDynamicSharedMemorySize, ATT_SMEM);

    tsplit_kernel<<<dim3(16,16,48), dim3(32,8)>>>(attn_w,   whA, wlA, 512, 512);
    tsplit_kernel<<<dim3(64,16,6),  dim3(32,8)>>>(ff_w1,    wh1, wl1, 512, 2048);
    tsplit_kernel<<<dim3(16,64,6),  dim3(32,8)>>>(ff_w2,    wh2, wl2, 2048, 512);
    tsplit_kernel<<<dim3(16,4,1),   dim3(32,8)>>>(expand_w, whe, wle, 128, 512);
    csplit_kernel<<<MROWS*128/256, 256>>>(memory, inh, inl, MROWS*128);

    auto G = [&](const bf16* AH, const bf16* AL, const bf16* WH, const bf16* WL,
                 const float* bi, const float* rs, float* Cf, bf16* CH, bf16* CL,
                 int K, int N, int act){
        tc_gemm<<<dim3(N/BN, MROWS/BM), 256, GEMM_SMEM>>>(AH, AL, WH, WL, bi, rs, Cf, CH, CL, K, N, act);
    };
    const dim3 ga(8, 128);

    G(inh, inl, whe, wle, expand_b, nullptr, nullptr, memh, meml, 128, 512, 1);

    const float* tin = target;
    for (int l=0; l<NLAYERS; l++){
        const size_t wo = (size_t)l*8*262144;
        const float* ab = attn_b + (size_t)l*8*DDIM;
        const float* lw = ln_w + (size_t)l*3*DDIM;
        const float* lb = ln_b + (size_t)l*3*DDIM;

        // self-attention (fused QKV)
        ln_kernel<<<MROWS,128>>>(tin, lw, lb, x, xh, xl);
        G(xh, xl, whA+wo, wlA+wo, ab, nullptr, nullptr, qkvh, qkvl, 512, 1536, 0);
        attn_mma<<<ga,128,ATT_SMEM>>>(qkvh, qkvl, 1536, qkvh+512, qkvl+512, 1536,
                                      qkvh+1024, qkvl+1024, 1536, aoh, aol, 1);
        G(aoh, aol, whA+wo+3ull*262144, wlA+wo+3ull*262144, ab+3*DDIM, x, t, nullptr, nullptr, 512, 512, 0);

        // cross-attention (fused KV)
        ln_kernel<<<MROWS,128>>>(t, lw+DDIM, lb+DDIM, x, xh, xl);
        G(xh, xl, whA+wo+4ull*262144, wlA+wo+4ull*262144, ab+4*DDIM, nullptr, nullptr, qkvh, qkvl, 512, 512, 0);
        G(memh, meml, whA+wo+5ull*262144, wlA+wo+5ull*262144, ab+5*DDIM, nullptr, nullptr, kvh, kvl, 512, 1024, 0);
        attn_mma<<<ga,128,ATT_SMEM>>>(qkvh, qkvl, 512, kvh, kvl, 1024,
                                      kvh+512, kvl+512, 1024, aoh, aol, 0);
        G(aoh, aol, whA+wo+7ull*262144, wlA+wo+7ull*262144, ab+7*DDIM, x, t, nullptr, nullptr, 512, 512, 0);

        // feed-forward
        ln_kernel<<<MROWS,128>>>(t, lw+2*DDIM, lb+2*DDIM, x, xh, xl);
        G(xh, xl, wh1+(size_t)l*DDIM*FFF, wl1+(size_t)l*DDIM*FFF, ff_b1+(size_t)l*FFF,
          nullptr, nullptr, ffh, ffl, 512, 2048, 1);
        float* dst = (l==NLAYERS-1) ? out : t;
        G(ffh, ffl, wh2+(size_t)l*FFF*DDIM, wl2+(size_t)l*FFF*DDIM, ff_b2+(size_t)l*DDIM,
          nullptr, dst, nullptr, nullptr, 2048, 512, 2);
        tin = t;
    }
}

// round 10
// speedup vs baseline: 4.5169x; 1.0013x over previous
#include <cuda_runtime.h>
#include <cuda_bf16.h>
#include <cstdint>
#include <math.h>

#define BB 16
#define DDIM 512
#define FFF 2048
#define NLAYERS 6
#define MROWS (BB*512)

typedef __nv_bfloat16 bf16;
typedef __nv_bfloat162 bf162;

// ---------------- scratch ----------------
__device__ __align__(256) float g_t [MROWS*DDIM];
__device__ __align__(256) float g_x [MROWS*DDIM];
__device__ __align__(256) bf16 g_xh [MROWS*DDIM];
__device__ __align__(256) bf16 g_xl [MROWS*DDIM];
__device__ __align__(256) bf16 g_qkvh[MROWS*1536];
__device__ __align__(256) bf16 g_qkvl[MROWS*1536];
__device__ __align__(256) bf16 g_kvh [MROWS*1024];
__device__ __align__(256) bf16 g_kvl [MROWS*1024];
__device__ __align__(256) bf16 g_aoh[MROWS*DDIM];
__device__ __align__(256) bf16 g_aol[MROWS*DDIM];
__device__ __align__(256) bf16 g_memh[MROWS*DDIM];
__device__ __align__(256) bf16 g_meml[MROWS*DDIM];
__device__ __align__(256) bf16 g_ffh[MROWS*FFF];
__device__ __align__(256) bf16 g_ffl[MROWS*FFF];
__device__ __align__(256) bf16 g_inh[MROWS*128];
__device__ __align__(256) bf16 g_inl[MROWS*128];
__device__ __align__(256) bf16 g_wh_attn[48*512*512];
__device__ __align__(256) bf16 g_wl_attn[48*512*512];
__device__ __align__(256) bf16 g_wh_ff1 [6*2048*512];
__device__ __align__(256) bf16 g_wl_ff1 [6*2048*512];
__device__ __align__(256) bf16 g_wh_ff2 [6*512*2048];
__device__ __align__(256) bf16 g_wl_ff2 [6*512*2048];
__device__ __align__(256) bf16 g_wh_exp [512*128];
__device__ __align__(256) bf16 g_wl_exp [512*128];

// ---------------- helpers ----------------
__device__ __forceinline__ uint32_t smem_u32(const void* p){
    uint32_t a; asm("{ .reg .u64 t; cvta.to.shared.u64 t, %1; cvt.u32.u64 %0, t; }":"=r"(a):"l"(p)); return a;
}
__device__ __forceinline__ void ldm_x4(uint32_t* r, uint32_t addr){
    asm volatile("ldmatrix.sync.aligned.m8n8.x4.shared.b16 {%0,%1,%2,%3}, [%4];"
        : "=r"(r[0]),"=r"(r[1]),"=r"(r[2]),"=r"(r[3]) : "r"(addr));
}
__device__ __forceinline__ void ldm_x4t(uint32_t* r, uint32_t addr){
    asm volatile("ldmatrix.sync.aligned.m8n8.x4.trans.shared.b16 {%0,%1,%2,%3}, [%4];"
        : "=r"(r[0]),"=r"(r[1]),"=r"(r[2]),"=r"(r[3]) : "r"(addr));
}
__device__ __forceinline__ void cpa16(uint32_t dst, const void* src){
    asm volatile("cp.async.cg.shared.global [%0], [%1], 16;" :: "r"(dst), "l"(src));
}
__device__ __forceinline__ void mma_bf16(float* d, const uint32_t* a, uint32_t b0, uint32_t b1){
    asm volatile(
        "mma.sync.aligned.m16n8k16.row.col.f32.bf16.bf16.f32 "
        "{%0,%1,%2,%3}, {%4,%5,%6,%7}, {%8,%9}, {%0,%1,%2,%3};"
        : "+f"(d[0]), "+f"(d[1]), "+f"(d[2]), "+f"(d[3])
        : "r"(a[0]), "r"(a[1]), "r"(a[2]), "r"(a[3]), "r"(b0), "r"(b1));
}
__device__ __forceinline__ uint32_t pack2(bf16 a, bf16 b){ bf162 h; h.x=a; h.y=b; return *(uint32_t*)&h; }
__device__ __forceinline__ bf16 bfh(float v){ return __float2bfloat16_rn(v); }
__device__ __forceinline__ float bff(bf16 v){ return __bfloat162float(v); }

// ---------------- transpose + split weights ----------------
__global__ void tsplit_kernel(const float* __restrict__ W, bf16* __restrict__ Hi,
                              bf16* __restrict__ Lo, int K, int N)
{
    __shared__ float t[32][33];
    const float* Wm = W + (size_t)blockIdx.z*K*N;
    bf16* Hm = Hi + (size_t)blockIdx.z*K*N;
    bf16* Lm = Lo + (size_t)blockIdx.z*K*N;
    int n0=blockIdx.x*32, k0=blockIdx.y*32, x=threadIdx.x, y=threadIdx.y;
#pragma unroll
    for (int i=0;i<32;i+=8) t[y+i][x] = Wm[(size_t)(k0+y+i)*N + n0+x];
    __syncthreads();
#pragma unroll
    for (int i=0;i<32;i+=8){
        float v = t[x][y+i];
        bf16 h = bfh(v);
        Hm[(size_t)(n0+y+i)*K + k0+x] = h;
        Lm[(size_t)(n0+y+i)*K + k0+x] = bfh(v - bff(h));
    }
}
__global__ void csplit_kernel(const float* __restrict__ X, bf16* __restrict__ H,
                              bf16* __restrict__ L, int n)
{
    int i = blockIdx.x*blockDim.x + threadIdx.x;
    if (i < n){
        float v = X[i];
        bf16 h = bfh(v);
        H[i] = h; L[i] = bfh(v - bff(h));
    }
}

// ---------------- GEMM (reduced live registers; 2 CTAs/SM) ----------------
#define BM 128
#define BN 128
#define BK 32
#define SROW 80
#define OPSZ (128*SROW)
#define STG (4*OPSZ)
#define GEMM_SMEM (2*STG)

__global__ __launch_bounds__(256, 2)
void tc_gemm(const bf16* __restrict__ AHg, const bf16* __restrict__ ALg,
             const bf16* __restrict__ WH, const bf16* __restrict__ WL,
             const float* __restrict__ bias, const float* __restrict__ res,
             float* __restrict__ Cf, bf16* __restrict__ CH, bf16* __restrict__ CL,
             int K, int N, int act)
{
    extern __shared__ char sm[];
    const uint32_t sbase = smem_u32(sm);
    const int tid = threadIdx.x, lane = tid&31, wid = tid>>5;
    const int gid = lane>>2, tq = lane&3;
    const int wm = wid&1, wn = wid>>1;
    const int m0 = blockIdx.y*BM, n0 = blockIdx.x*BN;
    const bf16* Ah = AHg + (size_t)m0*K;
    const bf16* Al = ALg + (size_t)m0*K;
    const bf16* Bh = WH + (size_t)n0*K;
    const bf16* Bl = WL + (size_t)n0*K;
    const int KT = K/BK;

    const int lrow = tid>>2, lc = tid&3;
    auto LOAD = [&](int kt){
        uint32_t st = sbase + (kt&1)*STG;
#pragma unroll
        for (int i=0;i<2;i++){
            int row = lrow + i*64;
            uint32_t off = (uint32_t)row*SROW + lc*16;
            size_t go = (size_t)row*K + kt*BK + lc*8;
            cpa16(st+off, Ah+go);
            cpa16(st+OPSZ+off, Al+go);
            cpa16(st+2*OPSZ+off, Bh+go);
            cpa16(st+3*OPSZ+off, Bl+go);
        }
        asm volatile("cp.async.commit_group;" ::: "memory");
    };
    const uint32_t aoff = (uint32_t)((wm*64 + (lane&15))*SROW + ((lane>>4)*16));
    const uint32_t boff = (uint32_t)((wn*32 + ((lane>>4)*8) + (lane&7))*SROW + (((lane>>3)&1)*16));

    float acc[4][4][4] = {};
    LOAD(0);
    for (int kt=0; kt<KT; kt++){
        if (kt+1 < KT) LOAD(kt+1);
        if (kt+1 < KT) asm volatile("cp.async.wait_group 1;" ::: "memory");
        else           asm volatile("cp.async.wait_group 0;" ::: "memory");
        __syncthreads();
        const uint32_t st = sbase + (kt&1)*STG;
#pragma unroll
        for (int k16=0; k16<2; k16++){
            const uint32_t ko = k16*32;
            uint32_t ah[4][4], al[4][4];
#pragma unroll
            for (int i=0;i<4;i++){
                ldm_x4(ah[i], st + aoff + i*16*SROW + ko);
                ldm_x4(al[i], st + OPSZ + aoff + i*16*SROW + ko);
            }
            // B fragments loaded per j-pair to cap live registers (~8 vs 16)
#pragma unroll
            for (int jj=0; jj<2; jj++){
                uint32_t bh4[4], bl4[4];
                ldm_x4(bh4, st + 2*OPSZ + boff + jj*16*SROW + ko);
                ldm_x4(bl4, st + 3*OPSZ + boff + jj*16*SROW + ko);
#pragma unroll
                for (int jh=0; jh<2; jh++){
                    const int j = jj*2 + jh;
                    uint32_t b0 = bh4[2*jh], b1 = bh4[2*jh+1];
                    uint32_t c0 = bl4[2*jh], c1 = bl4[2*jh+1];
#pragma unroll
                    for (int i=0;i<4;i++){
                        mma_bf16(acc[i][j], ah[i], b0, b1);
                        mma_bf16(acc[i][j], ah[i], c0, c1);
                        mma_bf16(acc[i][j], al[i], b0, b1);
                    }
                }
            }
        }
        __syncthreads();
    }
#pragma unroll
    for (int i=0;i<4;i++){
        const int r0 = m0 + wm*64 + i*16 + gid;
#pragma unroll
        for (int j=0;j<4;j++){
            const int c = n0 + wn*32 + j*8 + 2*tq;
            float b0 = bias[c], b1 = bias[c+1];
            float v[4] = {acc[i][j][0]+b0, acc[i][j][1]+b1, acc[i][j][2]+b0, acc[i][j][3]+b1};
            if (res){
                const float* rp0 = res + (size_t)r0*N + c;
                const float* rp1 = res + (size_t)(r0+8)*N + c;
                v[0]+=rp0[0]; v[1]+=rp0[1]; v[2]+=rp1[0]; v[3]+=rp1[1];
            }
            if (act==1){
#pragma unroll
                for (int u=0;u<4;u++) v[u] = v[u]>0.f ? v[u] : 0.01f*v[u];
            } else if (act==2){
#pragma unroll
                for (int u=0;u<4;u++) v[u] = 2.f*(v[u]>0.f ? v[u] : 0.01f*v[u]);
            }
            if (Cf){
                *(float2*)(Cf + (size_t)r0*N + c)     = make_float2(v[0], v[1]);
                *(float2*)(Cf + (size_t)(r0+8)*N + c) = make_float2(v[2], v[3]);
            }
            if (CH){
                bf16 h0=bfh(v[0]), h1=bfh(v[1]), h2=bfh(v[2]), h3=bfh(v[3]);
                *(uint32_t*)(CH + (size_t)r0*N + c)     = pack2(h0,h1);
                *(uint32_t*)(CH + (size_t)(r0+8)*N + c) = pack2(h2,h3);
                *(uint32_t*)(CL + (size_t)r0*N + c) =
                    pack2(bfh(v[0]-bff(h0)), bfh(v[1]-bff(h1)));
                *(uint32_t*)(CL + (size_t)(r0+8)*N + c) =
                    pack2(bfh(v[2]-bff(h2)), bfh(v[3]-bff(h3)));
            }
        }
    }
}

// ---------------- LayerNorm ----------------
__global__ void ln_kernel(const float* __restrict__ X, const float* __restrict__ w,
                          const float* __restrict__ b, float* __restrict__ Y,
                          bf16* __restrict__ YH, bf16* __restrict__ YL)
{
    const int row = blockIdx.x, tid = threadIdx.x;
    float4 v = ((const float4*)(X + (size_t)row*512))[tid];
    float s = v.x+v.y+v.z+v.w, ss = v.x*v.x+v.y*v.y+v.z*v.z+v.w*v.w;
#pragma unroll
    for (int o=16;o>0;o>>=1){ s+=__shfl_xor_sync(~0u,s,o); ss+=__shfl_xor_sync(~0u,ss,o); }
    __shared__ float rs[4], rss[4];
    int wd=tid>>5, ln=tid&31;
    if (ln==0){ rs[wd]=s; rss[wd]=ss; }
    __syncthreads();
    s=rs[0]+rs[1]+rs[2]+rs[3]; ss=rss[0]+rss[1]+rss[2]+rss[3];
    float mean=s*(1.f/512.f), var=ss*(1.f/512.f)-mean*mean, inv=rsqrtf(var+1e-5f);
    float4 wv=((const float4*)w)[tid], bv=((const float4*)b)[tid], y;
    y.x=(v.x-mean)*inv*wv.x+bv.x; y.y=(v.y-mean)*inv*wv.y+bv.y;
    y.z=(v.z-mean)*inv*wv.z+bv.z; y.w=(v.w-mean)*inv*wv.w+bv.w;
    ((float4*)(Y + (size_t)row*512))[tid] = y;
    bf16 h0=bfh(y.x), h1=bfh(y.y), h2=bfh(y.z), h3=bfh(y.w);
    uint32_t* HH = (uint32_t*)(YH + (size_t)row*512);
    uint32_t* LL = (uint32_t*)(YL + (size_t)row*512);
    HH[tid*2]   = pack2(h0,h1);
    HH[tid*2+1] = pack2(h2,h3);
    LL[tid*2]   = pack2(bfh(y.x-bff(h0)), bfh(y.y-bff(h1)));
    LL[tid*2+1] = pack2(bfh(y.z-bff(h2)), bfh(y.w-bff(h3)));
}

// ---------------- tensor-core flash attention (proven, fixed addressing) ----
#define AST 72
#define RSZ (64*AST*2)
#define QSH 0
#define QSL (1*RSZ)
#define KSH (2*RSZ)
#define KSL (3*RSZ)
#define VSH (4*RSZ)
#define VSL (5*RSZ)
#define ATT_SMEM (6*RSZ)

__global__ __launch_bounds__(128)
void attn_mma(const bf16* __restrict__ Qh, const bf16* __restrict__ Ql, int qs,
              const bf16* __restrict__ Kh, const bf16* __restrict__ Kl, int ks,
              const bf16* __restrict__ Vh, const bf16* __restrict__ Vl, int vs,
              bf16* __restrict__ OH, bf16* __restrict__ OL, int causal)
{
    extern __shared__ char smc[];
    const uint32_t sb = smem_u32(smc);
    bf16* smb = (bf16*)smc;
    const int qt = blockIdx.x, bh = blockIdx.y;
    const int b = bh >> 3, h = bh & 7;
    const int tid = threadIdx.x, lane = tid & 31, wid = tid >> 5;
    const int gid = lane >> 2, tq = lane & 3;
    const size_t qrow0 = (size_t)b*512 + h*64 + qt*8;
    const size_t krowb = (size_t)b*512 + h*64;

    for (int i = tid; i < 512; i += 128){
        int r = i >> 3, c = (i & 7) * 8;
        size_t g = (qrow0 + (r>>3))*qs + (r&7)*64 + c;
        *(uint4*)(smb + (QSH/2) + r*AST + c) = *(const uint4*)(Qh + g);
        *(uint4*)(smb + (QSL/2) + r*AST + c) = *(const uint4*)(Ql + g);
    }
    __syncthreads();

    const uint32_t qoff = sb + (uint32_t)(((wid*16 + (lane&15))*AST + (lane>>4)*8)*2);
    const uint32_t koff = sb + (uint32_t)(((((lane>>4)*8) + (lane&7))*AST + ((lane>>3)&1)*8)*2);
    const uint32_t voff = sb + (uint32_t)(((((lane&7) + ((lane>>3)&1)*8)*AST) + (lane>>4)*8)*2);

    uint32_t qfh[4][4], qfl[4][4];
#pragma unroll
    for (int g=0; g<4; g++){
        ldm_x4(qfh[g], qoff + QSH + g*32);
        ldm_x4(qfl[g], qoff + QSL + g*32);
    }

    float m0=-INFINITY, m1=-INFINITY, l0=0.f, l1=0.f;
    float acc[8][4] = {};
    const int ktmax = causal ? qt : 7;

    for (int kt=0; kt<=ktmax; kt++){
        __syncthreads();
        const size_t krow = krowb + kt*8;
        for (int i = tid; i < 512; i += 128){
            int r = i >> 3, c = (i & 7) * 8;
            size_t gk = (krow + (r>>3))*ks + (r&7)*64 + c;
            size_t gv = (krow + (r>>3))*vs + (r&7)*64 + c;
            *(uint4*)(smb + (KSH/2) + r*AST + c) = *(const uint4*)(Kh + gk);
            *(uint4*)(smb + (KSL/2) + r*AST + c) = *(const uint4*)(Kl + gk);
            *(uint4*)(smb + (VSH/2) + r*AST + c) = *(const uint4*)(Vh + gv);
            *(uint4*)(smb + (VSL/2) + r*AST + c) = *(const uint4*)(Vl + gv);
        }
        __syncthreads();

        float s[8][4] = {};
#pragma unroll
        for (int g=0; g<4; g++){
#pragma unroll
            for (int kk=0; kk<4; kk++){
                uint32_t bk[4], bkl[4];
                ldm_x4(bk,  koff + KSH + g*(16*AST*2) + kk*32);
                ldm_x4(bkl, koff + KSL + g*(16*AST*2) + kk*32);
                mma_bf16(s[2*g],   qfh[kk], bk[0],  bk[1]);
                mma_bf16(s[2*g],   qfh[kk], bkl[0], bkl[1]);
                mma_bf16(s[2*g],   qfl[kk], bk[0],  bk[1]);
                mma_bf16(s[2*g+1], qfh[kk], bk[2],  bk[3]);
                mma_bf16(s[2*g+1], qfh[kk], bkl[2], bkl[3]);
                mma_bf16(s[2*g+1], qfl[kk], bk[2],  bk[3]);
            }
        }

        const int rl0 = wid*16 + gid;
        float mx0=-INFINITY, mx1=-INFINITY;
#pragma unroll
        for (int j=0; j<8; j++){
#pragma unroll
            for (int c=0; c<4; c++) s[j][c] *= 0.03125f;
            if (causal && kt == qt){
                int col = j*8 + 2*tq;
                if (col   > rl0)   s[j][0] = -1e9f;
                if (col+1 > rl0)   s[j][1] = -1e9f;
                if (col   > rl0+8) s[j][2] = -1e9f;
                if (col+1 > rl0+8) s[j][3] = -1e9f;
            }
            mx0 = fmaxf(mx0, fmaxf(s[j][0], s[j][1]));
            mx1 = fmaxf(mx1, fmaxf(s[j][2], s[j][3]));
        }
        mx0 = fmaxf(mx0, __shfl_xor_sync(~0u, mx0, 1));
        mx0 = fmaxf(mx0, __shfl_xor_sync(~0u, mx0, 2));
        mx1 = fmaxf(mx1, __shfl_xor_sync(~0u, mx1, 1));
        mx1 = fmaxf(mx1, __shfl_xor_sync(~0u, mx1, 2));
        float mn0 = fmaxf(m0, mx0), mn1 = fmaxf(m1, mx1);
        float f0 = __expf(m0 - mn0), f1 = __expf(m1 - mn1);
        m0 = mn0; m1 = mn1; l0 *= f0; l1 *= f1;
#pragma unroll
        for (int j=0; j<8; j++){
            s[j][0] = __expf(s[j][0]-m0); s[j][1] = __expf(s[j][1]-m0);
            s[j][2] = __expf(s[j][2]-m1); s[j][3] = __expf(s[j][3]-m1);
            l0 += s[j][0] + s[j][1];
            l1 += s[j][2] + s[j][3];
            acc[j][0]*=f0; acc[j][1]*=f0; acc[j][2]*=f1; acc[j][3]*=f1;
        }

#pragma unroll
        for (int g=0; g<4; g++){
            float* t0 = s[2*g]; float* t1 = s[2*g+1];
            bf16 h00=bfh(t0[0]), h01=bfh(t0[1]), h02=bfh(t0[2]), h03=bfh(t0[3]);
            bf16 h10=bfh(t1[0]), h11=bfh(t1[1]), h12=bfh(t1[2]), h13=bfh(t1[3]);
            uint32_t aph[4] = { pack2(h00,h01), pack2(h02,h03), pack2(h10,h11), pack2(h12,h13) };
            uint32_t apl[4] = {
                pack2(bfh(t0[0]-bff(h00)), bfh(t0[1]-bff(h01))),
                pack2(bfh(t0[2]-bff(h02)), bfh(t0[3]-bff(h03))),
                pack2(bfh(t1[0]-bff(h10)), bfh(t1[1]-bff(h11))),
                pack2(bfh(t1[2]-bff(h12)), bfh(t1[3]-bff(h13))) };
#pragma unroll
            for (int jj=0; jj<4; jj++){
                uint32_t bv[4], bvl[4];
                ldm_x4t(bv,  voff + VSH + g*(16*AST*2) + jj*32);
                ldm_x4t(bvl, voff + VSL + g*(16*AST*2) + jj*32);
                mma_bf16(acc[2*jj],   aph, bv[0],  bv[1]);
                mma_bf16(acc[2*jj],   aph, bvl[0], bvl[1]);
                mma_bf16(acc[2*jj],   apl, bv[0],  bv[1]);
                mma_bf16(acc[2*jj+1], aph, bv[2],  bv[3]);
                mma_bf16(acc[2*jj+1], aph, bvl[2], bvl[3]);
                mma_bf16(acc[2*jj+1], apl, bv[2],  bv[3]);
            }
        }
    }

    l0 += __shfl_xor_sync(~0u, l0, 1); l0 += __shfl_xor_sync(~0u, l0, 2);
    l1 += __shfl_xor_sync(~0u, l1, 1); l1 += __shfl_xor_sync(~0u, l1, 2);
    float inv0 = 1.f/l0, inv1 = 1.f/l1;
    const size_t orow = qrow0 + wid*2;
#pragma unroll
    for (int j=0; j<8; j++){
        int col = gid*64 + j*8 + 2*tq;
        float o0 = acc[j][0]*inv0, o1 = acc[j][1]*inv0;
        float o2 = acc[j][2]*inv1, o3 = acc[j][3]*inv1;
        bf16 h0=bfh(o0), h1=bfh(o1), h2=bfh(o2), h3=bfh(o3);
        *(uint32_t*)(OH + orow*512 + col)     = pack2(h0,h1);
        *(uint32_t*)(OH + (orow+1)*512 + col) = pack2(h2,h3);
        *(uint32_t*)(OL + orow*512 + col)     = pack2(bfh(o0-bff(h0)), bfh(o1-bff(h1)));
        *(uint32_t*)(OL + (orow+1)*512 + col) = pack2(bfh(o2-bff(h2)), bfh(o3-bff(h3)));
    }
}

// ---------------- orchestration ----------------
extern "C" void kernel_launch(void* const* d_in, const int* in_sizes, int n_in,
                              void* d_out, int out_size)
{
    const float* memory   = (const float*)d_in[0];
    const float* target   = (const float*)d_in[1];
    const float* expand_w = (const float*)d_in[3];
    const float* expand_b = (const float*)d_in[4];
    const float* ln_w     = (const float*)d_in[5];
    const float* ln_b     = (const float*)d_in[6];
    const float* attn_w   = (const float*)d_in[7];
    const float* attn_b   = (const float*)d_in[8];
    const float* ff_w1    = (const float*)d_in[9];
    const float* ff_b1    = (const float*)d_in[10];
    const float* ff_w2    = (const float*)d_in[11];
    const float* ff_b2    = (const float*)d_in[12];
    float* out = (float*)d_out;

    float *t,*x;
    bf16 *xh,*xl,*qkvh,*qkvl,*kvh,*kvl,*aoh,*aol,*memh,*meml,*ffh,*ffl,*inh,*inl;
    bf16 *whA,*wlA,*wh1,*wl1,*wh2,*wl2,*whe,*wle;
    cudaGetSymbolAddress((void**)&t,  g_t);
    cudaGetSymbolAddress((void**)&x,  g_x);
    cudaGetSymbolAddress((void**)&xh, g_xh);
    cudaGetSymbolAddress((void**)&xl, g_xl);
    cudaGetSymbolAddress((void**)&qkvh,g_qkvh);
    cudaGetSymbolAddress((void**)&qkvl,g_qkvl);
    cudaGetSymbolAddress((void**)&kvh,g_kvh);
    cudaGetSymbolAddress((void**)&kvl,g_kvl);
    cudaGetSymbolAddress((void**)&aoh,g_aoh);
    cudaGetSymbolAddress((void**)&aol,g_aol);
    cudaGetSymbolAddress((void**)&memh,g_memh);
    cudaGetSymbolAddress((void**)&meml,g_meml);
    cudaGetSymbolAddress((void**)&ffh,g_ffh);
    cudaGetSymbolAddress((void**)&ffl,g_ffl);
    cudaGetSymbolAddress((void**)&inh,g_inh);
    cudaGetSymbolAddress((void**)&inl,g_inl);
    cudaGetSymbolAddress((void**)&whA,g_wh_attn);
    cudaGetSymbolAddress((void**)&wlA,g_wl_attn);
    cudaGetSymbolAddress((void**)&wh1,g_wh_ff1);
    cudaGetSymbolAddress((void**)&wl1,g_wl_ff1);
    cudaGetSymbolAddress((void**)&wh2,g_wh_ff2);
    cudaGetSymbolAddress((void**)&wl2,g_wl_ff2);
    cudaGetSymbolAddress((void**)&whe,g_wh_exp);
    cudaGetSymbolAddress((void**)&wle,g_wl_exp);

    cudaFuncSetAttribute(tc_gemm,  cudaFuncAttributeMaxDynamicSharedMemorySize, GEMM_SMEM);
    cudaFuncSetAttribute(attn_mma, cudaFuncAttributeMaxDynamicSharedMemorySize, ATT_SMEM);

    tsplit_kernel<<<dim3(16,16,48), dim3(32,8)>>>(attn_w,   whA, wlA, 512, 512);
    tsplit_kernel<<<dim3(64,16,6),  dim3(32,8)>>>(ff_w1,    wh1, wl1, 512, 2048);
    tsplit_kernel<<<dim3(16,64,6),  dim3(32,8)>>>(ff_w2,    wh2, wl2, 2048, 512);
    tsplit_kernel<<<dim3(16,4,1),   dim3(32,8)>>>(expand_w, whe, wle, 128, 512);
    csplit_kernel<<<MROWS*128/256, 256>>>(memory, inh, inl, MROWS*128);

    auto G = [&](const bf16* AH, const bf16* AL, const bf16* WH, const bf16* WL,
                 const float* bi, const float* rs, float* Cf, bf16* CH, bf16* CL,
                 int K, int N, int act){
        tc_gemm<<<dim3(N/BN, MROWS/BM), 256, GEMM_SMEM>>>(AH, AL, WH, WL, bi, rs, Cf, CH, CL, K, N, act);
    };
    const dim3 ga(8, 128);

    G(inh, inl, whe, wle, expand_b, nullptr, nullptr, memh, meml, 128, 512, 1);

    const float* tin = target;
    for (int l=0; l<NLAYERS; l++){
        const size_t wo = (size_t)l*8*262144;
        const float* ab = attn_b + (size_t)l*8*DDIM;
        const float* lw = ln_w + (size_t)l*3*DDIM;
        const float* lb = ln_b + (size_t)l*3*DDIM;

        // self-attention (fused QKV)
        ln_kernel<<<MROWS,128>>>(tin, lw, lb, x, xh, xl);
        G(xh, xl, whA+wo, wlA+wo, ab, nullptr, nullptr, qkvh, qkvl, 512, 1536, 0);
        attn_mma<<<ga,128,ATT_SMEM>>>(qkvh, qkvl, 1536, qkvh+512, qkvl+512, 1536,
                                      qkvh+1024, qkvl+1024, 1536, aoh, aol, 1);
        G(aoh, aol, whA+wo+3ull*262144, wlA+wo+3ull*262144, ab+3*DDIM, x, t, nullptr, nullptr, 512, 512, 0);

        // cross-attention (fused KV)
        ln_kernel<<<MROWS,128>>>(t, lw+DDIM, lb+DDIM, x, xh, xl);
        G(xh, xl, whA+wo+4ull*262144, wlA+wo+4ull*262144, ab+4*DDIM, nullptr, nullptr, qkvh, qkvl, 512, 512, 0);
        G(memh, meml, whA+wo+5ull*262144, wlA+wo+5ull*262144, ab+5*DDIM, nullptr, nullptr, kvh, kvl, 512, 1024, 0);
        attn_mma<<<ga,128,ATT_SMEM>>>(qkvh, qkvl, 512, kvh, kvl, 1024,
                                      kvh+512, kvl+512, 1024, aoh, aol, 0);
        G(aoh, aol, whA+wo+7ull*262144, wlA+wo+7ull*262144, ab+7*DDIM, x, t, nullptr, nullptr, 512, 512, 0);

        // feed-forward
        ln_kernel<<<MROWS,128>>>(t, lw+2*DDIM, lb+2*DDIM, x, xh, xl);
        G(xh, xl, wh1+(size_t)l*DDIM*FFF, wl1+(size_t)l*DDIM*FFF, ff_b1+(size_t)l*FFF,
          nullptr, nullptr, ffh, ffl, 512, 2048, 1);
        float* dst = (l==NLAYERS-1) ? out : t;
        G(ffh, ffl, wh2+(size_t)l*FFF*DDIM, wl2+(size_t)l*FFF*DDIM, ff_b2+(size_t)l*DDIM,
          nullptr, dst, nullptr, nullptr, 2048, 512, 2);
        tin = t;
    }
}